// round 5
// baseline (speedup 1.0000x reference)
#include <cuda_runtime.h>
#include <cstdint>
#include <math.h>

#define NN 2048
#define KK 48
#define HH 128
#define NODES 8192
#define FFW 512
#define NTILES 4096            // NODES/2
#define SCALE_INV (1.0f/30.0f)

// -------- scratch (device globals) --------
__device__ uint32_t g_m1p[(size_t)NODES * KK * 64];   // 100.7 MB, bf16 pairs (m1 activations)
__device__ float    g_h [(size_t)NODES * HH];         // 4 MB
__device__ float    g_t [(size_t)NODES * FFW];        // 16 MB

// -------- helpers --------
__device__ __forceinline__ uint32_t f2tf(float x) {
    uint32_t u;
    asm("cvt.rna.tf32.f32 %0, %1;" : "=r"(u) : "f"(x));
    return u;
}
__device__ __forceinline__ uint32_t bpack(float lo, float hi) {  // bits[31:16]=hi, [15:0]=lo
    uint32_t r;
    asm("cvt.rn.bf16x2.f32 %0, %1, %2;" : "=r"(r) : "f"(hi), "f"(lo));
    return r;
}
__device__ __forceinline__ void cp16(void* s, const void* g) {
    uint32_t sa = (uint32_t)__cvta_generic_to_shared(s);
    asm volatile("cp.async.cg.shared.global [%0], [%1], 16;" :: "r"(sa), "l"(g));
}
#define CP_COMMIT() asm volatile("cp.async.commit_group;")
#define CP_WAIT1()  asm volatile("cp.async.wait_group 1;" ::: "memory")

__device__ __forceinline__ void mma8(float c[4],
                                     uint32_t a0, uint32_t a1, uint32_t a2, uint32_t a3,
                                     uint32_t b0, uint32_t b1) {
    asm volatile(
        "mma.sync.aligned.m16n8k8.row.col.f32.tf32.tf32.f32 "
        "{%0,%1,%2,%3},{%4,%5,%6,%7},{%8,%9},{%0,%1,%2,%3};"
        : "+f"(c[0]), "+f"(c[1]), "+f"(c[2]), "+f"(c[3])
        : "r"(a0), "r"(a1), "r"(a2), "r"(a3), "r"(b0), "r"(b1));
}

__device__ __forceinline__ float gelu_tanh(float x) {   // approximate=True
    float x3 = x * x * x;
    return 0.5f * x * (1.0f + tanhf(0.7978845608028654f * (x + 0.044715f * x3)));
}
__device__ __forceinline__ float gelu_erf(float x) {    // approximate=False
    return 0.5f * x * (1.0f + erff(x * 0.7071067811865476f));
}

// Generic slab-loop mma: MI m-fragments (16 rows each), NJ n-fragments (8 cols each).
template<int MI, int NJ, bool CVTA, bool CVTB>
__device__ __forceinline__ void mma_block(
    const float* __restrict__ A, int lda, const float* __restrict__ B, int ldb,
    int nslab, int kw0, int mbase, int nbase, int g, int tg, float (*acc)[NJ][4])
{
    #pragma unroll 1
    for (int s = 0; s < nslab; s++) {
        const int kk = s * 8;
        uint32_t a[MI][4];
        #pragma unroll
        for (int i = 0; i < MI; i++) {
            int r0 = mbase + i * 16 + g;
            float f0 = A[r0 * lda + kk + tg];
            float f1 = A[(r0 + 8) * lda + kk + tg];
            float f2 = A[r0 * lda + kk + tg + 4];
            float f3 = A[(r0 + 8) * lda + kk + tg + 4];
            a[i][0] = CVTA ? f2tf(f0) : __float_as_uint(f0);
            a[i][1] = CVTA ? f2tf(f1) : __float_as_uint(f1);
            a[i][2] = CVTA ? f2tf(f2) : __float_as_uint(f2);
            a[i][3] = CVTA ? f2tf(f3) : __float_as_uint(f3);
        }
        #pragma unroll
        for (int j = 0; j < NJ; j++) {
            int n0 = nbase + j * 8;
            float fb0 = B[(kw0 + kk + tg) * ldb + n0 + g];
            float fb1 = B[(kw0 + kk + tg + 4) * ldb + n0 + g];
            uint32_t b0 = CVTB ? f2tf(fb0) : __float_as_uint(fb0);
            uint32_t b1 = CVTB ? f2tf(fb1) : __float_as_uint(fb1);
            #pragma unroll
            for (int i = 0; i < MI; i++)
                mma8(acc[i][j], a[i][0], a[i][1], a[i][2], a[i][3], b0, b1);
        }
    }
}

// ============================================================================
// Kernel 1: layer1, pipelined. A = concat(h_nb, h_E) as 4 half-k stages
// (gather lo/hi, hE lo/hi) double-buffered via cp.async. W1 resident (tf32).
// Epilogue: bias+gelu -> g_m1p (bf16 pairs).
// smem: W1 256x136 (139264) | buf0 128x68 f32 (34816) | buf1 (34816) |
//       ptr0 128x8 (1024) | ptr1 (1024)  = 210944 B
// ============================================================================
__device__ __forceinline__ void e1_issue(float* buf, int hc, int node0,
    const float* const* ptab, const float* __restrict__ hE, int t)
{
    int r = t >> 1, half = t & 1;
    char* dst = (char*)buf + r * 272 + half * 128;
    const char* src;
    if (hc < 2) {
        src = (const char*)(ptab[r]) + (hc & 1) * 256 + half * 128;
    } else {
        int er = r & 63; er = er < KK ? er : KK - 1;
        int node = node0 + (r >> 6);
        src = (const char*)(hE + ((size_t)(node * KK + er)) * HH + (hc & 1) * 64) + half * 128;
    }
    #pragma unroll
    for (int s = 0; s < 8; s++) cp16(dst + s * 16, src + s * 16);
}

__global__ __launch_bounds__(256, 1) void k_edge1(
    const float* __restrict__ hV, const float* __restrict__ hE,
    const int* __restrict__ Eidx, const float* __restrict__ W1,
    const float* __restrict__ b1)
{
    extern __shared__ char smem[];
    uint32_t* sW   = (uint32_t*)smem;                       // 256 x 136 tf32
    float*    bufA = (float*)(smem + 139264);
    float*    bufB = (float*)(smem + 139264 + 34816);
    const float** sPtrArr[2];
    sPtrArr[0] = (const float**)(smem + 208896);
    sPtrArr[1] = (const float**)(smem + 209920);

    const int tid  = threadIdx.x;
    const int lane = tid & 31, wid = tid >> 5;
    const int g = lane >> 2, tg = lane & 3;
    const int wm = wid >> 2, wn = wid & 3;

    // W1 -> smem (tf32), float4 loads
    for (int idx = tid; idx < 256 * 32; idx += 256) {
        int row = idx >> 5, c4 = idx & 31;
        float4 w = ((const float4*)W1)[idx];
        uint32_t* d = &sW[row * 136 + c4 * 4];
        d[0] = f2tf(w.x); d[1] = f2tf(w.y); d[2] = f2tf(w.z); d[3] = f2tf(w.w);
    }
    // first tile gather pointers
    int p0 = blockIdx.x;
    if (p0 < NTILES && tid < 128) {
        int er = tid & 63, node = 2 * p0 + (tid >> 6);
        int nb = (er < KK) ? Eidx[node * KK + er] : 0;
        sPtrArr[0][tid] = hV + ((size_t)((node >> 11) * NN + nb)) * HH;
    }
    __syncthreads();
    if (p0 < NTILES) e1_issue(bufA, 0, 2 * p0, sPtrArr[0], hE, tid);
    CP_COMMIT();

    int par = 0;
    for (int p = blockIdx.x; p < NTILES; p += gridDim.x) {
        const int node0 = 2 * p;
        const int pn = p + (int)gridDim.x;
        const float* const* ptrCur  = sPtrArr[par];
        const float* const* ptrNext = sPtrArr[par ^ 1];
        float acc[4][4][4];
        #pragma unroll
        for (int i = 0; i < 4; i++)
            #pragma unroll
            for (int j = 0; j < 4; j++)
                #pragma unroll
                for (int q = 0; q < 4; q++) acc[i][j][q] = 0.0f;

        int nbv = 0;
        #pragma unroll 1
        for (int hc = 0; hc < 4; hc++) {
            float* nbuf = ((hc + 1) & 1) ? bufB : bufA;
            if (hc < 3)            e1_issue(nbuf, hc + 1, node0, ptrCur, hE, tid);
            else if (pn < NTILES)  e1_issue(nbuf, 0, 2 * pn, ptrNext, hE, tid);
            CP_COMMIT();
            CP_WAIT1();
            __syncthreads();
            if (hc == 0 && pn < NTILES && tid < 128) {
                int er = tid & 63, node = 2 * pn + (tid >> 6);
                nbv = (er < KK) ? Eidx[node * KK + er] : 0;
            }
            if (hc == 1 && pn < NTILES && tid < 128) {
                int node = 2 * pn + (tid >> 6);
                const_cast<const float**>(ptrNext)[tid] =
                    hV + ((size_t)((node >> 11) * NN + nbv)) * HH;
            }
            mma_block<4, 4, true, false>((hc & 1) ? bufB : bufA, 68,
                                         (const float*)sW, 136, 8, hc * 64,
                                         wm * 64, wn * 32, g, tg, acc);
            __syncthreads();
        }

        // epilogue: bias + gelu + bf16 store
        #pragma unroll
        for (int j = 0; j < 4; j++) {
            const int col = wn * 32 + j * 8 + 2 * tg;
            const float bb0 = b1[col], bb1 = b1[col + 1];
            #pragma unroll
            for (int i = 0; i < 4; i++) {
                const int r0 = wm * 64 + i * 16 + g;
                const int er0 = r0 & 63, er1 = (r0 + 8) & 63;
                const int nd = node0 + (r0 >> 6);
                float v0 = gelu_tanh(acc[i][j][0] + bb0);
                float v1 = gelu_tanh(acc[i][j][1] + bb1);
                float v2 = gelu_tanh(acc[i][j][2] + bb0);
                float v3 = gelu_tanh(acc[i][j][3] + bb1);
                if (er0 < KK)
                    g_m1p[((size_t)(nd * KK + er0)) * 64 + (col >> 1)] = bpack(v0, v1);
                if (er1 < KK)
                    g_m1p[((size_t)(nd * KK + er1)) * 64 + (col >> 1)] = bpack(v2, v3);
            }
        }
        par ^= 1;
    }
}

// ============================================================================
// Kernel 2: layers 2+3 fused + mask + K-reduce + /30 + residual -> g_h.
// m1 (bf16) register-staged double-buffered; m2 overlays the two half-buffers.
// smem: W2 (69632) | W3 (69632) | buf0/buf1 = m2 region (69632) | mask (512)
//       = 209408 B
// ============================================================================
__device__ __forceinline__ void e2_ldg(uint4 R[4], int p, int half, int t) {
    int r = t >> 1, er = r & 63; er = er < KK ? er : KK - 1;
    int node = 2 * p + (r >> 6);
    const uint4* src = (const uint4*)(g_m1p + ((size_t)(node * KK + er)) * 64
                                      + half * 32 + (t & 1) * 16);
    #pragma unroll
    for (int q = 0; q < 4; q++) R[q] = src[q];
}
__device__ __forceinline__ void e2_sts(const uint4 R[4], float* buf, int t) {
    int r = t >> 1;
    float2* dst = (float2*)((char*)buf + r * 272);
    int cbase = (t & 1) * 16;
    #pragma unroll
    for (int q = 0; q < 4; q++) {
        uint32_t u[4] = {R[q].x, R[q].y, R[q].z, R[q].w};
        #pragma unroll
        for (int w = 0; w < 4; w++) {
            int c = cbase + q * 4 + w;
            dst[c] = make_float2(__uint_as_float(u[w] << 16),
                                 __uint_as_float(u[w] & 0xffff0000u));
        }
    }
}

__global__ __launch_bounds__(256, 1) void k_edge2(
    const float* __restrict__ hV, const float* __restrict__ mask_att,
    const float* __restrict__ W2, const float* __restrict__ b2,
    const float* __restrict__ W3, const float* __restrict__ b3)
{
    extern __shared__ char smem[];
    uint32_t* sW2  = (uint32_t*)smem;
    uint32_t* sW3  = (uint32_t*)(smem + 69632);
    float*    bufA = (float*)(smem + 139264);
    float*    bufB = (float*)(smem + 139264 + 34816);
    float*    sM2  = (float*)(smem + 139264);     // 128 x 136 overlay
    float*    sMask = (float*)(smem + 208896);

    const int tid  = threadIdx.x;
    const int lane = tid & 31, wid = tid >> 5;
    const int g = lane >> 2, tg = lane & 3;
    const int wm = wid >> 2, wn = wid & 3;

    for (int idx = tid; idx < 128 * 32; idx += 256) {
        int row = idx >> 5, c4 = idx & 31;
        float4 w2 = ((const float4*)W2)[idx];
        float4 w3 = ((const float4*)W3)[idx];
        uint32_t* d2 = &sW2[row * 136 + c4 * 4];
        uint32_t* d3 = &sW3[row * 136 + c4 * 4];
        d2[0] = f2tf(w2.x); d2[1] = f2tf(w2.y); d2[2] = f2tf(w2.z); d2[3] = f2tf(w2.w);
        d3[0] = f2tf(w3.x); d3[1] = f2tf(w3.y); d3[2] = f2tf(w3.z); d3[3] = f2tf(w3.w);
    }

    uint4 R[4];
    float mreg = 0.0f;
    int p0 = blockIdx.x;
    if (p0 < NTILES) {
        e2_ldg(R, p0, 0, tid);
        if (tid < 128) {
            int er = tid & 63, node = 2 * p0 + (tid >> 6);
            mreg = (er < KK) ? mask_att[node * KK + er] : 0.0f;
        }
    }

    for (int p = blockIdx.x; p < NTILES; p += gridDim.x) {
        const int node0 = 2 * p;
        const int pn = p + (int)gridDim.x;

        __syncthreads();            // prev tile layer3 done with sM2 region
        e2_sts(R, bufA, tid);
        if (tid < 128) sMask[tid] = mreg;
        uint4 Rh[4];
        e2_ldg(Rh, p, 1, tid);      // overlaps layer2-lo mma
        __syncthreads();

        float acc[4][4][4];
        #pragma unroll
        for (int i = 0; i < 4; i++)
            #pragma unroll
            for (int j = 0; j < 4; j++)
                #pragma unroll
                for (int q = 0; q < 4; q++) acc[i][j][q] = 0.0f;

        mma_block<4, 4, false, false>(bufA, 68, (const float*)sW2, 136, 8, 0,
                                      wm * 64, wn * 32, g, tg, acc);
        e2_sts(Rh, bufB, tid);
        __syncthreads();
        mma_block<4, 4, false, false>(bufB, 68, (const float*)sW2, 136, 8, 64,
                                      wm * 64, wn * 32, g, tg, acc);
        __syncthreads();

        // m2 = gelu(acc + b2) into sM2 (LD 136)
        #pragma unroll
        for (int j = 0; j < 4; j++) {
            const int col = wn * 32 + j * 8 + 2 * tg;
            const float bb0 = b2[col], bb1 = b2[col + 1];
            #pragma unroll
            for (int i = 0; i < 4; i++) {
                const int r0 = wm * 64 + i * 16 + g;
                sM2[r0 * 136 + col]           = __uint_as_float(f2tf(gelu_tanh(acc[i][j][0] + bb0)));
                sM2[r0 * 136 + col + 1]       = __uint_as_float(f2tf(gelu_tanh(acc[i][j][1] + bb1)));
                sM2[(r0 + 8) * 136 + col]     = __uint_as_float(f2tf(gelu_tanh(acc[i][j][2] + bb0)));
                sM2[(r0 + 8) * 136 + col + 1] = __uint_as_float(f2tf(gelu_tanh(acc[i][j][3] + bb1)));
            }
        }
        // prefetch next tile (overlaps layer3)
        if (pn < NTILES) {
            e2_ldg(R, pn, 0, tid);
            if (tid < 128) {
                int er = tid & 63, node = 2 * pn + (tid >> 6);
                mreg = (er < KK) ? mask_att[node * KK + er] : 0.0f;
            }
        }
        __syncthreads();

        #pragma unroll
        for (int i = 0; i < 4; i++)
            #pragma unroll
            for (int j = 0; j < 4; j++)
                #pragma unroll
                for (int q = 0; q < 4; q++) acc[i][j][q] = 0.0f;
        mma_block<4, 4, false, false>(sM2, 136, (const float*)sW3, 136, 16, 0,
                                      wm * 64, wn * 32, g, tg, acc);

        // mask + reduce over K (warp wm owns node node0+wm)
        const int node = node0 + wm;
        #pragma unroll
        for (int j = 0; j < 4; j++) {
            const int col = wn * 32 + j * 8 + 2 * tg;
            const float bb0 = b3[col], bb1 = b3[col + 1];
            float s0 = 0.f, s1 = 0.f;
            #pragma unroll
            for (int i = 0; i < 4; i++) {
                const int r0 = wm * 64 + i * 16 + g;
                const float m0 = sMask[r0], m8 = sMask[r0 + 8];
                s0 += m0 * (acc[i][j][0] + bb0) + m8 * (acc[i][j][2] + bb0);
                s1 += m0 * (acc[i][j][1] + bb1) + m8 * (acc[i][j][3] + bb1);
            }
            #pragma unroll
            for (int m = 4; m <= 16; m <<= 1) {
                s0 += __shfl_xor_sync(0xffffffffu, s0, m);
                s1 += __shfl_xor_sync(0xffffffffu, s1, m);
            }
            if (lane < 4) {
                const size_t base = (size_t)node * HH + col;
                g_h[base]     = hV[base]     + s0 * SCALE_INV;
                g_h[base + 1] = hV[base + 1] + s1 * SCALE_INV;
            }
        }
    }
}

// ============================================================================
// Kernel 3: FFN layer 1. CTA tile 128x256 (grid 64 m-blocks x 2 n-halves),
// block 512 (16 warps, 4x4), single wave.
// smem: sW 128x264 (135168) | sA 128x136 (69632) = 204800 B
// ============================================================================
__global__ __launch_bounds__(512, 1) void k_ff1(
    const float* __restrict__ Win, const float* __restrict__ bin)
{
    extern __shared__ char smem[];
    uint32_t* sW = (uint32_t*)smem;
    uint32_t* sA = (uint32_t*)(smem + 135168);

    const int tid  = threadIdx.x;
    const int lane = tid & 31, wid = tid >> 5;
    const int g = lane >> 2, tg = lane & 3;
    const int wm = wid >> 2, wn = wid & 3;        // 4 (m32) x 4 (n64)
    const int mblk = blockIdx.x >> 1;
    const int nh   = (blockIdx.x & 1) * 256;

    for (int idx = tid; idx < 128 * 64; idx += 512) {
        int row = idx >> 6, c4 = idx & 63;
        float4 w = *(const float4*)(Win + (size_t)row * FFW + nh + c4 * 4);
        uint32_t* d = &sW[row * 264 + c4 * 4];
        d[0] = f2tf(w.x); d[1] = f2tf(w.y); d[2] = f2tf(w.z); d[3] = f2tf(w.w);
    }
    for (int idx = tid; idx < 128 * 32; idx += 512) {
        int row = idx >> 5, c4 = idx & 31;
        float4 v = *(const float4*)(g_h + (size_t)(mblk * 128 + row) * HH + c4 * 4);
        uint32_t* d = &sA[row * 136 + c4 * 4];
        d[0] = f2tf(v.x); d[1] = f2tf(v.y); d[2] = f2tf(v.z); d[3] = f2tf(v.w);
    }
    __syncthreads();

    float acc[2][8][4];
    #pragma unroll
    for (int i = 0; i < 2; i++)
        #pragma unroll
        for (int j = 0; j < 8; j++)
            #pragma unroll
            for (int q = 0; q < 4; q++) acc[i][j][q] = 0.0f;

    mma_block<2, 8, false, false>((const float*)sA, 136, (const float*)sW, 264,
                                  16, 0, wm * 32, wn * 64, g, tg, acc);

    #pragma unroll
    for (int j = 0; j < 8; j++) {
        const int col = wn * 64 + j * 8 + 2 * tg;
        const int ng = nh + col;
        const float bb0 = bin[ng], bb1 = bin[ng + 1];
        #pragma unroll
        for (int i = 0; i < 2; i++) {
            const int row = mblk * 128 + wm * 32 + i * 16 + g;
            float2* d0 = (float2*)(g_t + (size_t)row * FFW + ng);
            float2* d1 = (float2*)(g_t + (size_t)(row + 8) * FFW + ng);
            *d0 = make_float2(gelu_erf(acc[i][j][0] + bb0), gelu_erf(acc[i][j][1] + bb1));
            *d1 = make_float2(gelu_erf(acc[i][j][2] + bb0), gelu_erf(acc[i][j][3] + bb1));
        }
    }
}

// ============================================================================
// Kernel 4: FFN layer 2 + residual + mask_V -> out. CTA tile 64x128, grid 128,
// K=512 in 4 pipelined (cp.async double-buffered) 128-k chunks.
// smem: sW0 (69632) | sW1 (69632) | sA0 (34816) | sA1 (34816) = 208896 B
// ============================================================================
__device__ __forceinline__ void ff2_issue(float* wbuf, float* abuf, int c, int mblk,
    const float* __restrict__ Wout, const float* __restrict__ gt, int t)
{
    {
        int r = t >> 1, half = t & 1;
        char* dst = (char*)wbuf + r * 544 + half * 256;
        const char* src = (const char*)(Wout + ((size_t)(c * 128 + r)) * HH + half * 64);
        #pragma unroll
        for (int s = 0; s < 16; s++) cp16(dst + s * 16, src + s * 16);
    }
    {
        int r = t >> 2, q = t & 3;
        char* dst = (char*)abuf + r * 544 + q * 128;
        const char* src = (const char*)(gt + ((size_t)(mblk * 64 + r)) * FFW + c * 128 + q * 32);
        #pragma unroll
        for (int s = 0; s < 8; s++) cp16(dst + s * 16, src + s * 16);
    }
}

__global__ __launch_bounds__(256, 1) void k_ff2(
    const float* __restrict__ Wout, const float* __restrict__ bout,
    const float* __restrict__ maskV, float* __restrict__ out)
{
    extern __shared__ char smem[];
    float* sW0 = (float*)smem;
    float* sW1 = (float*)(smem + 69632);
    float* sA0 = (float*)(smem + 139264);
    float* sA1 = (float*)(smem + 174080);

    const int tid  = threadIdx.x;
    const int lane = tid & 31, wid = tid >> 5;
    const int g = lane >> 2, tg = lane & 3;
    const int wm = wid >> 2, wn = wid & 3;     // 2 (m32) x 4 (n32)
    const int mblk = blockIdx.x;

    ff2_issue(sW0, sA0, 0, mblk, Wout, g_t, tid);
    CP_COMMIT();

    float acc[2][4][4];
    #pragma unroll
    for (int i = 0; i < 2; i++)
        #pragma unroll
        for (int j = 0; j < 4; j++)
            #pragma unroll
            for (int q = 0; q < 4; q++) acc[i][j][q] = 0.0f;

    #pragma unroll 1
    for (int c = 0; c < 4; c++) {
        if (c < 3) {
            float* wb = ((c + 1) & 1) ? sW1 : sW0;
            float* ab = ((c + 1) & 1) ? sA1 : sA0;
            ff2_issue(wb, ab, c + 1, mblk, Wout, g_t, tid);
        }
        CP_COMMIT();
        CP_WAIT1();
        __syncthreads();
        mma_block<2, 4, true, true>((c & 1) ? sA1 : sA0, 136,
                                    (c & 1) ? sW1 : sW0, 136, 16, 0,
                                    wm * 32, wn * 32, g, tg, acc);
        __syncthreads();
    }

    #pragma unroll
    for (int j = 0; j < 4; j++) {
        const int col = wn * 32 + j * 8 + 2 * tg;
        const float bb0 = bout[col], bb1 = bout[col + 1];
        #pragma unroll
        for (int i = 0; i < 2; i++) {
            const int row0 = mblk * 64 + wm * 32 + i * 16 + g;
            #pragma unroll
            for (int h = 0; h < 2; h++) {
                const int row = row0 + h * 8;
                const float mv = maskV[row];
                const size_t base = (size_t)row * HH + col;
                float v0 = acc[i][j][h * 2 + 0] + bb0 + g_h[base];
                float v1 = acc[i][j][h * 2 + 1] + bb1 + g_h[base + 1];
                float2* d = (float2*)(out + base);
                *d = make_float2(mv * v0, mv * v1);
            }
        }
    }
}

// ============================================================================
extern "C" void kernel_launch(void* const* d_in, const int* in_sizes, int n_in,
                              void* d_out, int out_size)
{
    const float* hV    = (const float*)d_in[0];
    const float* hE    = (const float*)d_in[1];
    const int*   Eidx  = (const int*)  d_in[2];
    const float* maskV = (const float*)d_in[3];
    const float* maskA = (const float*)d_in[4];
    const float* W1    = (const float*)d_in[5];
    const float* b1    = (const float*)d_in[6];
    const float* W2    = (const float*)d_in[7];
    const float* b2    = (const float*)d_in[8];
    const float* W3    = (const float*)d_in[9];
    const float* b3    = (const float*)d_in[10];
    const float* Win   = (const float*)d_in[11];
    const float* bin   = (const float*)d_in[12];
    const float* Wout  = (const float*)d_in[13];
    const float* bout  = (const float*)d_in[14];
    float* out = (float*)d_out;

    const int smE1 = 210944;
    const int smE2 = 209408;
    const int smF1 = 204800;
    const int smF2 = 208896;

    cudaFuncSetAttribute(k_edge1, cudaFuncAttributeMaxDynamicSharedMemorySize, smE1);
    cudaFuncSetAttribute(k_edge2, cudaFuncAttributeMaxDynamicSharedMemorySize, smE2);
    cudaFuncSetAttribute(k_ff1,   cudaFuncAttributeMaxDynamicSharedMemorySize, smF1);
    cudaFuncSetAttribute(k_ff2,   cudaFuncAttributeMaxDynamicSharedMemorySize, smF2);

    k_edge1<<<152, 256, smE1>>>(hV, hE, Eidx, W1, b1);
    k_edge2<<<152, 256, smE2>>>(hV, maskA, W2, b2, W3, b3);
    k_ff1  <<<128, 512, smF1>>>(Win, bin);
    k_ff2  <<<128, 256, smF2>>>(Wout, bout, maskV, out);
}

// round 10
// speedup vs baseline: 1.6032x; 1.6032x over previous
#include <cuda_runtime.h>
#include <cstdint>
#include <math.h>

#define NN 2048
#define KK 48
#define HH 128
#define NODES 8192
#define FFW 512
#define NTILES 4096            // NODES/2
#define SCALE_INV (1.0f/30.0f)

// LD rules (floats, mod 32):
//   LD % 32 == 4  -> conflict-free A-frags (bank 4g+tg) AND B-frags (bank 4tg+g)
//   full-k buffers: 132; half-k buffers: 68; ff1 weight tile: 260

// -------- scratch (device globals) --------
__device__ uint32_t g_m1p[(size_t)NODES * KK * 64];   // 100.7 MB, bf16 pairs
__device__ float    g_h [(size_t)NODES * HH];         // 4 MB
__device__ float    g_t [(size_t)NODES * FFW];        // 16 MB

// -------- helpers --------
__device__ __forceinline__ uint32_t f2tf(float x) {
    uint32_t u;
    asm("cvt.rna.tf32.f32 %0, %1;" : "=r"(u) : "f"(x));
    return u;
}
__device__ __forceinline__ uint32_t bpack(float lo, float hi) {  // [31:16]=hi, [15:0]=lo
    uint32_t r;
    asm("cvt.rn.bf16x2.f32 %0, %1, %2;" : "=r"(r) : "f"(hi), "f"(lo));
    return r;
}
__device__ __forceinline__ float blo(uint32_t u) { return __uint_as_float(u << 16); }
__device__ __forceinline__ float bhi(uint32_t u) { return __uint_as_float(u & 0xffff0000u); }

__device__ __forceinline__ void cp16(void* s, const void* g) {
    uint32_t sa = (uint32_t)__cvta_generic_to_shared(s);
    asm volatile("cp.async.cg.shared.global [%0], [%1], 16;" :: "r"(sa), "l"(g));
}
#define CP_COMMIT() asm volatile("cp.async.commit_group;")
#define CP_WAIT1()  asm volatile("cp.async.wait_group 1;" ::: "memory")

__device__ __forceinline__ void mma8(float c[4],
                                     uint32_t a0, uint32_t a1, uint32_t a2, uint32_t a3,
                                     uint32_t b0, uint32_t b1) {
    asm volatile(
        "mma.sync.aligned.m16n8k8.row.col.f32.tf32.tf32.f32 "
        "{%0,%1,%2,%3},{%4,%5,%6,%7},{%8,%9},{%0,%1,%2,%3};"
        : "+f"(c[0]), "+f"(c[1]), "+f"(c[2]), "+f"(c[3])
        : "r"(a0), "r"(a1), "r"(a2), "r"(a3), "r"(b0), "r"(b1));
}

__device__ __forceinline__ float gelu_tanh(float x) {
    float x3 = x * x * x;
    return 0.5f * x * (1.0f + tanhf(0.7978845608028654f * (x + 0.044715f * x3)));
}
__device__ __forceinline__ float gelu_erf(float x) {
    return 0.5f * x * (1.0f + erff(x * 0.7071067811865476f));
}

template<int MI, int NJ, bool CVTA, bool CVTB>
__device__ __forceinline__ void mma_block(
    const float* __restrict__ A, int lda, const float* __restrict__ B, int ldb,
    int nslab, int kw0, int mbase, int nbase, int g, int tg, float (*acc)[NJ][4])
{
    #pragma unroll 1
    for (int s = 0; s < nslab; s++) {
        const int kk = s * 8;
        uint32_t a[MI][4];
        #pragma unroll
        for (int i = 0; i < MI; i++) {
            int r0 = mbase + i * 16 + g;
            float f0 = A[r0 * lda + kk + tg];
            float f1 = A[(r0 + 8) * lda + kk + tg];
            float f2 = A[r0 * lda + kk + tg + 4];
            float f3 = A[(r0 + 8) * lda + kk + tg + 4];
            a[i][0] = CVTA ? f2tf(f0) : __float_as_uint(f0);
            a[i][1] = CVTA ? f2tf(f1) : __float_as_uint(f1);
            a[i][2] = CVTA ? f2tf(f2) : __float_as_uint(f2);
            a[i][3] = CVTA ? f2tf(f3) : __float_as_uint(f3);
        }
        #pragma unroll
        for (int j = 0; j < NJ; j++) {
            int n0 = nbase + j * 8;
            float fb0 = B[(kw0 + kk + tg) * ldb + n0 + g];
            float fb1 = B[(kw0 + kk + tg + 4) * ldb + n0 + g];
            uint32_t b0 = CVTB ? f2tf(fb0) : __float_as_uint(fb0);
            uint32_t b1 = CVTB ? f2tf(fb1) : __float_as_uint(fb1);
            #pragma unroll
            for (int i = 0; i < MI; i++)
                mma8(acc[i][j], a[i][0], a[i][1], a[i][2], a[i][3], b0, b1);
        }
    }
}

// ============================================================================
// Kernel 1: layer1, pipelined half-k stages via cp.async, W1 resident (tf32).
// Issue pattern: half-warp per 256B row-half (coalesced, 4 lines/instr).
// smem: W1 256x132 (135168) | bufA 128x68 (34816) | bufB (34816) |
//       ptr0 (1024) | ptr1 (1024) = 206848 B
// ============================================================================
__device__ __forceinline__ void e1_issue(float* buf, int hc, int node0,
    const float* const* ptab, const float* __restrict__ hE, int wid, int lane)
{
    const int sub = lane >> 4;       // 0/1: which of the 2 rows this instr covers
    const int c   = lane & 15;       // 16B chunk within the 256B half-row
    #pragma unroll
    for (int k = 0; k < 8; k++) {
        int r = 2 * (wid + 8 * k) + sub;
        char* dst = (char*)buf + r * 272 + c * 16;
        const char* src;
        if (hc < 2) {
            src = (const char*)(ptab[r]) + (hc & 1) * 256 + c * 16;
        } else {
            int er = r & 63; er = er < KK ? er : KK - 1;
            int node = node0 + (r >> 6);
            src = (const char*)(hE + ((size_t)(node * KK + er)) * HH + (hc & 1) * 64) + c * 16;
        }
        cp16(dst, src);
    }
}

__global__ __launch_bounds__(256, 1) void k_edge1(
    const float* __restrict__ hV, const float* __restrict__ hE,
    const int* __restrict__ Eidx, const float* __restrict__ W1,
    const float* __restrict__ b1)
{
    extern __shared__ char smem[];
    uint32_t* sW   = (uint32_t*)smem;                       // 256 x 132 tf32
    float*    bufA = (float*)(smem + 135168);
    float*    bufB = (float*)(smem + 135168 + 34816);
    const float** sPtrArr[2];
    sPtrArr[0] = (const float**)(smem + 204800);
    sPtrArr[1] = (const float**)(smem + 205824);

    const int tid  = threadIdx.x;
    const int lane = tid & 31, wid = tid >> 5;
    const int g = lane >> 2, tg = lane & 3;
    const int wm = wid >> 2, wn = wid & 3;

    for (int idx = tid; idx < 256 * 32; idx += 256) {
        int row = idx >> 5, c4 = idx & 31;
        float4 w = ((const float4*)W1)[idx];
        uint32_t* d = &sW[row * 132 + c4 * 4];
        d[0] = f2tf(w.x); d[1] = f2tf(w.y); d[2] = f2tf(w.z); d[3] = f2tf(w.w);
    }
    int p0 = blockIdx.x;
    if (p0 < NTILES && tid < 128) {
        int er = tid & 63, node = 2 * p0 + (tid >> 6);
        int nb = (er < KK) ? Eidx[node * KK + er] : 0;
        sPtrArr[0][tid] = hV + ((size_t)((node >> 11) * NN + nb)) * HH;
    }
    __syncthreads();
    if (p0 < NTILES) e1_issue(bufA, 0, 2 * p0, sPtrArr[0], hE, wid, lane);
    CP_COMMIT();

    int par = 0;
    for (int p = blockIdx.x; p < NTILES; p += gridDim.x) {
        const int node0 = 2 * p;
        const int pn = p + (int)gridDim.x;
        const float* const* ptrCur  = sPtrArr[par];
        const float* const* ptrNext = sPtrArr[par ^ 1];
        float acc[4][4][4];
        #pragma unroll
        for (int i = 0; i < 4; i++)
            #pragma unroll
            for (int j = 0; j < 4; j++)
                #pragma unroll
                for (int q = 0; q < 4; q++) acc[i][j][q] = 0.0f;

        int nbv = 0;
        #pragma unroll 1
        for (int hc = 0; hc < 4; hc++) {
            float* nbuf = ((hc + 1) & 1) ? bufB : bufA;
            if (hc < 3)            e1_issue(nbuf, hc + 1, node0, ptrCur, hE, wid, lane);
            else if (pn < NTILES)  e1_issue(nbuf, 0, 2 * pn, ptrNext, hE, wid, lane);
            CP_COMMIT();
            CP_WAIT1();
            __syncthreads();
            if (hc == 0 && pn < NTILES && tid < 128) {
                int er = tid & 63, node = 2 * pn + (tid >> 6);
                nbv = (er < KK) ? Eidx[node * KK + er] : 0;
            }
            if (hc == 1 && pn < NTILES && tid < 128) {
                int node = 2 * pn + (tid >> 6);
                const_cast<const float**>(ptrNext)[tid] =
                    hV + ((size_t)((node >> 11) * NN + nbv)) * HH;
            }
            mma_block<4, 4, true, false>((hc & 1) ? bufB : bufA, 68,
                                         (const float*)sW, 132, 8, hc * 64,
                                         wm * 64, wn * 32, g, tg, acc);
            __syncthreads();
        }

        #pragma unroll
        for (int j = 0; j < 4; j++) {
            const int col = wn * 32 + j * 8 + 2 * tg;
            const float bb0 = b1[col], bb1 = b1[col + 1];
            #pragma unroll
            for (int i = 0; i < 4; i++) {
                const int r0 = wm * 64 + i * 16 + g;
                const int er0 = r0 & 63, er1 = (r0 + 8) & 63;
                const int nd = node0 + (r0 >> 6);
                float v0 = gelu_tanh(acc[i][j][0] + bb0);
                float v1 = gelu_tanh(acc[i][j][1] + bb1);
                float v2 = gelu_tanh(acc[i][j][2] + bb0);
                float v3 = gelu_tanh(acc[i][j][3] + bb1);
                if (er0 < KK)
                    g_m1p[((size_t)(nd * KK + er0)) * 64 + (col >> 1)] = bpack(v0, v1);
                if (er1 < KK)
                    g_m1p[((size_t)(nd * KK + er1)) * 64 + (col >> 1)] = bpack(v2, v3);
            }
        }
        par ^= 1;
    }
}

// ============================================================================
// Kernel 2: layers 2+3 fused + mask + K-reduce + /30 + residual -> g_h.
// m1 (bf16) prefetched into registers (warp-per-row, uint2/lane), expanded via
// conflict-free STS.128 into sA (LD 132); m2 overwrites sA after layer 2.
// smem: W2 (67584) | W3 (67584) | sA 128x132 (67584) | mask (512) = 203264 B
// ============================================================================
__device__ __forceinline__ void e2_prefetch(uint2 R[16], float& mreg, int p,
    const float* __restrict__ mask_att, int wid, int lane, int tid)
{
    #pragma unroll
    for (int i = 0; i < 16; i++) {
        int r = wid + 8 * i;
        int er = r & 63; er = er < KK ? er : KK - 1;
        int node = 2 * p + (r >> 6);
        R[i] = ((const uint2*)(g_m1p + ((size_t)(node * KK + er)) * 64))[lane];
    }
    if (tid < 128) {
        int er = tid & 63, node = 2 * p + (tid >> 6);
        mreg = (er < KK) ? mask_att[node * KK + er] : 0.0f;
    }
}

__global__ __launch_bounds__(256, 1) void k_edge2(
    const float* __restrict__ hV, const float* __restrict__ mask_att,
    const float* __restrict__ W2, const float* __restrict__ b2,
    const float* __restrict__ W3, const float* __restrict__ b3)
{
    extern __shared__ char smem[];
    uint32_t* sW2 = (uint32_t*)smem;
    uint32_t* sW3 = (uint32_t*)(smem + 67584);
    float*    sA  = (float*)(smem + 135168);      // 128 x 132
    float*    sMask = (float*)(smem + 202752);

    const int tid  = threadIdx.x;
    const int lane = tid & 31, wid = tid >> 5;
    const int g = lane >> 2, tg = lane & 3;
    const int wm = wid >> 2, wn = wid & 3;

    for (int idx = tid; idx < 128 * 32; idx += 256) {
        int row = idx >> 5, c4 = idx & 31;
        float4 w2 = ((const float4*)W2)[idx];
        float4 w3 = ((const float4*)W3)[idx];
        uint32_t* d2 = &sW2[row * 132 + c4 * 4];
        uint32_t* d3 = &sW3[row * 132 + c4 * 4];
        d2[0] = f2tf(w2.x); d2[1] = f2tf(w2.y); d2[2] = f2tf(w2.z); d2[3] = f2tf(w2.w);
        d3[0] = f2tf(w3.x); d3[1] = f2tf(w3.y); d3[2] = f2tf(w3.z); d3[3] = f2tf(w3.w);
    }

    uint2 R[16];
    float mreg = 0.0f;
    if (blockIdx.x < NTILES)
        e2_prefetch(R, mreg, blockIdx.x, mask_att, wid, lane, tid);

    for (int p = blockIdx.x; p < NTILES; p += gridDim.x) {
        const int node0 = 2 * p;
        const int pn = p + (int)gridDim.x;

        __syncthreads();   // prev tile's layer-3 reads of sA are done
        // expand bf16 m1 -> sA (warp-per-row, STS.128, conflict-free)
        #pragma unroll
        for (int i = 0; i < 16; i++) {
            int r = wid + 8 * i;
            float4 v = make_float4(blo(R[i].x), bhi(R[i].x), blo(R[i].y), bhi(R[i].y));
            *(float4*)(sA + r * 132 + lane * 4) = v;
        }
        if (tid < 128) sMask[tid] = mreg;
        __syncthreads();

        // prefetch next tile now; LDG latency hides under layers 2+3
        if (pn < NTILES)
            e2_prefetch(R, mreg, pn, mask_att, wid, lane, tid);

        // ---- layer 2 ----
        float acc[4][4][4];
        #pragma unroll
        for (int i = 0; i < 4; i++)
            #pragma unroll
            for (int j = 0; j < 4; j++)
                #pragma unroll
                for (int q = 0; q < 4; q++) acc[i][j][q] = 0.0f;
        mma_block<4, 4, false, false>(sA, 132, (const float*)sW2, 132, 16, 0,
                                      wm * 64, wn * 32, g, tg, acc);
        __syncthreads();

        // m2 = gelu(acc + b2) back into sA (tf32 bits)
        #pragma unroll
        for (int j = 0; j < 4; j++) {
            const int col = wn * 32 + j * 8 + 2 * tg;
            const float bb0 = b2[col], bb1 = b2[col + 1];
            #pragma unroll
            for (int i = 0; i < 4; i++) {
                const int r0 = wm * 64 + i * 16 + g;
                sA[r0 * 132 + col]           = __uint_as_float(f2tf(gelu_tanh(acc[i][j][0] + bb0)));
                sA[r0 * 132 + col + 1]       = __uint_as_float(f2tf(gelu_tanh(acc[i][j][1] + bb1)));
                sA[(r0 + 8) * 132 + col]     = __uint_as_float(f2tf(gelu_tanh(acc[i][j][2] + bb0)));
                sA[(r0 + 8) * 132 + col + 1] = __uint_as_float(f2tf(gelu_tanh(acc[i][j][3] + bb1)));
            }
        }
        __syncthreads();

        // ---- layer 3 ----
        #pragma unroll
        for (int i = 0; i < 4; i++)
            #pragma unroll
            for (int j = 0; j < 4; j++)
                #pragma unroll
                for (int q = 0; q < 4; q++) acc[i][j][q] = 0.0f;
        mma_block<4, 4, false, false>(sA, 132, (const float*)sW3, 132, 16, 0,
                                      wm * 64, wn * 32, g, tg, acc);

        // ---- mask + reduce over K ----
        const int node = node0 + wm;
        #pragma unroll
        for (int j = 0; j < 4; j++) {
            const int col = wn * 32 + j * 8 + 2 * tg;
            const float bb0 = b3[col], bb1 = b3[col + 1];
            float s0 = 0.f, s1 = 0.f;
            #pragma unroll
            for (int i = 0; i < 4; i++) {
                const int r0 = wm * 64 + i * 16 + g;
                const float m0 = sMask[r0], m8 = sMask[r0 + 8];
                s0 += m0 * (acc[i][j][0] + bb0) + m8 * (acc[i][j][2] + bb0);
                s1 += m0 * (acc[i][j][1] + bb1) + m8 * (acc[i][j][3] + bb1);
            }
            #pragma unroll
            for (int m = 4; m <= 16; m <<= 1) {
                s0 += __shfl_xor_sync(0xffffffffu, s0, m);
                s1 += __shfl_xor_sync(0xffffffffu, s1, m);
            }
            if (lane < 4) {
                const size_t base = (size_t)node * HH + col;
                g_h[base]     = hV[base]     + s0 * SCALE_INV;
                g_h[base + 1] = hV[base + 1] + s1 * SCALE_INV;
            }
        }
    }
}

// ============================================================================
// Kernel 3: FFN layer 1. CTA tile 128x256, grid 128 (single wave), block 512.
// smem: sW 128x260 (133120) | sA 128x132 (67584) = 200704 B
// ============================================================================
__global__ __launch_bounds__(512, 1) void k_ff1(
    const float* __restrict__ Win, const float* __restrict__ bin)
{
    extern __shared__ char smem[];
    uint32_t* sW = (uint32_t*)smem;
    uint32_t* sA = (uint32_t*)(smem + 133120);

    const int tid  = threadIdx.x;
    const int lane = tid & 31, wid = tid >> 5;
    const int g = lane >> 2, tg = lane & 3;
    const int wm = wid >> 2, wn = wid & 3;
    const int mblk = blockIdx.x >> 1;
    const int nh   = (blockIdx.x & 1) * 256;

    for (int idx = tid; idx < 128 * 64; idx += 512) {
        int row = idx >> 6, c4 = idx & 63;
        float4 w = *(const float4*)(Win + (size_t)row * FFW + nh + c4 * 4);
        uint32_t* d = &sW[row * 260 + c4 * 4];
        d[0] = f2tf(w.x); d[1] = f2tf(w.y); d[2] = f2tf(w.z); d[3] = f2tf(w.w);
    }
    for (int idx = tid; idx < 128 * 32; idx += 512) {
        int row = idx >> 5, c4 = idx & 31;
        float4 v = *(const float4*)(g_h + (size_t)(mblk * 128 + row) * HH + c4 * 4);
        uint32_t* d = &sA[row * 132 + c4 * 4];
        d[0] = f2tf(v.x); d[1] = f2tf(v.y); d[2] = f2tf(v.z); d[3] = f2tf(v.w);
    }
    __syncthreads();

    float acc[2][8][4];
    #pragma unroll
    for (int i = 0; i < 2; i++)
        #pragma unroll
        for (int j = 0; j < 8; j++)
            #pragma unroll
            for (int q = 0; q < 4; q++) acc[i][j][q] = 0.0f;

    mma_block<2, 8, false, false>((const float*)sA, 132, (const float*)sW, 260,
                                  16, 0, wm * 32, wn * 64, g, tg, acc);

    #pragma unroll
    for (int j = 0; j < 8; j++) {
        const int col = wn * 64 + j * 8 + 2 * tg;
        const int ng = nh + col;
        const float bb0 = bin[ng], bb1 = bin[ng + 1];
        #pragma unroll
        for (int i = 0; i < 2; i++) {
            const int row = mblk * 128 + wm * 32 + i * 16 + g;
            float2* d0 = (float2*)(g_t + (size_t)row * FFW + ng);
            float2* d1 = (float2*)(g_t + (size_t)(row + 8) * FFW + ng);
            *d0 = make_float2(gelu_erf(acc[i][j][0] + bb0), gelu_erf(acc[i][j][1] + bb1));
            *d1 = make_float2(gelu_erf(acc[i][j][2] + bb0), gelu_erf(acc[i][j][3] + bb1));
        }
    }
}

// ============================================================================
// Kernel 4: FFN layer 2 + residual + mask_V -> out. 4 pipelined k-chunks.
// smem: sW0 128x132 (67584) | sW1 (67584) | sA0 64x132 (33792) | sA1 (33792)
//       = 202752 B
// ============================================================================
__device__ __forceinline__ void ff2_issue(float* wbuf, float* abuf, int c, int mblk,
    const float* __restrict__ Wout, const float* __restrict__ gt, int t)
{
    {
        int r = t >> 1, half = t & 1;
        char* dst = (char*)wbuf + r * 528 + half * 256;
        const char* src = (const char*)(Wout + ((size_t)(c * 128 + r)) * HH + half * 64);
        #pragma unroll
        for (int s = 0; s < 16; s++) cp16(dst + s * 16, src + s * 16);
    }
    {
        int r = t >> 2, q = t & 3;
        char* dst = (char*)abuf + r * 528 + q * 128;
        const char* src = (const char*)(gt + ((size_t)(mblk * 64 + r)) * FFW + c * 128 + q * 32);
        #pragma unroll
        for (int s = 0; s < 8; s++) cp16(dst + s * 16, src + s * 16);
    }
}

__global__ __launch_bounds__(256, 1) void k_ff2(
    const float* __restrict__ Wout, const float* __restrict__ bout,
    const float* __restrict__ maskV, float* __restrict__ out)
{
    extern __shared__ char smem[];
    float* sW0 = (float*)smem;
    float* sW1 = (float*)(smem + 67584);
    float* sA0 = (float*)(smem + 135168);
    float* sA1 = (float*)(smem + 168960);

    const int tid  = threadIdx.x;
    const int lane = tid & 31, wid = tid >> 5;
    const int g = lane >> 2, tg = lane & 3;
    const int wm = wid >> 2, wn = wid & 3;
    const int mblk = blockIdx.x;

    ff2_issue(sW0, sA0, 0, mblk, Wout, g_t, tid);
    CP_COMMIT();

    float acc[2][4][4];
    #pragma unroll
    for (int i = 0; i < 2; i++)
        #pragma unroll
        for (int j = 0; j < 4; j++)
            #pragma unroll
            for (int q = 0; q < 4; q++) acc[i][j][q] = 0.0f;

    #pragma unroll 1
    for (int c = 0; c < 4; c++) {
        if (c < 3) {
            float* wb = ((c + 1) & 1) ? sW1 : sW0;
            float* ab = ((c + 1) & 1) ? sA1 : sA0;
            ff2_issue(wb, ab, c + 1, mblk, Wout, g_t, tid);
        }
        CP_COMMIT();
        CP_WAIT1();
        __syncthreads();
        mma_block<2, 4, true, true>((c & 1) ? sA1 : sA0, 132,
                                    (c & 1) ? sW1 : sW0, 132, 16, 0,
                                    wm * 32, wn * 32, g, tg, acc);
        __syncthreads();
    }

    #pragma unroll
    for (int j = 0; j < 4; j++) {
        const int col = wn * 32 + j * 8 + 2 * tg;
        const float bb0 = bout[col], bb1 = bout[col + 1];
        #pragma unroll
        for (int i = 0; i < 2; i++) {
            const int row0 = mblk * 64 + wm * 32 + i * 16 + g;
            #pragma unroll
            for (int h = 0; h < 2; h++) {
                const int row = row0 + h * 8;
                const float mv = maskV[row];
                const size_t base = (size_t)row * HH + col;
                float v0 = acc[i][j][h * 2 + 0] + bb0 + g_h[base];
                float v1 = acc[i][j][h * 2 + 1] + bb1 + g_h[base + 1];
                float2* d = (float2*)(out + base);
                *d = make_float2(mv * v0, mv * v1);
            }
        }
    }
}

// ============================================================================
extern "C" void kernel_launch(void* const* d_in, const int* in_sizes, int n_in,
                              void* d_out, int out_size)
{
    const float* hV    = (const float*)d_in[0];
    const float* hE    = (const float*)d_in[1];
    const int*   Eidx  = (const int*)  d_in[2];
    const float* maskV = (const float*)d_in[3];
    const float* maskA = (const float*)d_in[4];
    const float* W1    = (const float*)d_in[5];
    const float* b1    = (const float*)d_in[6];
    const float* W2    = (const float*)d_in[7];
    const float* b2    = (const float*)d_in[8];
    const float* W3    = (const float*)d_in[9];
    const float* b3    = (const float*)d_in[10];
    const float* Win   = (const float*)d_in[11];
    const float* bin   = (const float*)d_in[12];
    const float* Wout  = (const float*)d_in[13];
    const float* bout  = (const float*)d_in[14];
    float* out = (float*)d_out;

    const int smE1 = 206848;
    const int smE2 = 203264;
    const int smF1 = 200704;
    const int smF2 = 202752;

    cudaFuncSetAttribute(k_edge1, cudaFuncAttributeMaxDynamicSharedMemorySize, smE1);
    cudaFuncSetAttribute(k_edge2, cudaFuncAttributeMaxDynamicSharedMemorySize, smE2);
    cudaFuncSetAttribute(k_ff1,   cudaFuncAttributeMaxDynamicSharedMemorySize, smF1);
    cudaFuncSetAttribute(k_ff2,   cudaFuncAttributeMaxDynamicSharedMemorySize, smF2);

    k_edge1<<<152, 256, smE1>>>(hV, hE, Eidx, W1, b1);
    k_edge2<<<152, 256, smE2>>>(hV, maskA, W2, b2, W3, b3);
    k_ff1  <<<128, 512, smF1>>>(Win, bin);
    k_ff2  <<<128, 256, smF2>>>(Wout, bout, maskV, out);
}

// round 12
// speedup vs baseline: 1.6295x; 1.0164x over previous
#include <cuda_runtime.h>
#include <cstdint>
#include <math.h>

#define NN 2048
#define KK 48
#define HH 128
#define NODES 8192
#define FFW 512
#define NT4 2048               // NODES/4 (edge tiles, 4 nodes each)
#define SCALE_INV (1.0f/30.0f)

// Bank rule (u32 words, mod 32): LD % 32 == 4 -> conflict-free A-frags (4g+tg)
// and B-frags (4tg+g). Buffers: 36 (quarter-K rows), 68 (bf16-pair rows),
// 132 (full-k f32/tf32), 260 (ff1 weight tile).

// -------- scratch --------
__device__ uint32_t g_m1p[(size_t)NODES * KK * 64];   // bf16 pairs
__device__ float    g_h [(size_t)NODES * HH];
__device__ float    g_t [(size_t)NODES * FFW];

// -------- helpers --------
__device__ __forceinline__ uint32_t f2tf(float x) {
    uint32_t u;
    asm("cvt.rna.tf32.f32 %0, %1;" : "=r"(u) : "f"(x));
    return u;
}
__device__ __forceinline__ uint32_t bpack(float lo, float hi) {  // [31:16]=hi,[15:0]=lo
    uint32_t r;
    asm("cvt.rn.bf16x2.f32 %0, %1, %2;" : "=r"(r) : "f"(hi), "f"(lo));
    return r;
}
__device__ __forceinline__ void cp16(void* s, const void* g) {
    uint32_t sa = (uint32_t)__cvta_generic_to_shared(s);
    asm volatile("cp.async.cg.shared.global [%0], [%1], 16;" :: "r"(sa), "l"(g));
}
#define CP_COMMIT() asm volatile("cp.async.commit_group;")
#define CP_WAIT1()  asm volatile("cp.async.wait_group 1;" ::: "memory")

__device__ __forceinline__ void mma8(float c[4],
                                     uint32_t a0, uint32_t a1, uint32_t a2, uint32_t a3,
                                     uint32_t b0, uint32_t b1) {
    asm volatile(
        "mma.sync.aligned.m16n8k8.row.col.f32.tf32.tf32.f32 "
        "{%0,%1,%2,%3},{%4,%5,%6,%7},{%8,%9},{%0,%1,%2,%3};"
        : "+f"(c[0]), "+f"(c[1]), "+f"(c[2]), "+f"(c[3])
        : "r"(a0), "r"(a1), "r"(a2), "r"(a3), "r"(b0), "r"(b1));
}

__device__ __forceinline__ float gelu_tanh(float x) {
    float x3 = x * x * x;
    return 0.5f * x * (1.0f + tanhf(0.7978845608028654f * (x + 0.044715f * x3)));
}
__device__ __forceinline__ float gelu_erf(float x) {
    return 0.5f * x * (1.0f + erff(x * 0.7071067811865476f));
}

// f32/tf32-in-smem A, tf32-in-smem B
template<int MI, int NJ, bool CVTA, bool CVTB>
__device__ __forceinline__ void mma_block(
    const float* __restrict__ A, int lda, const float* __restrict__ B, int ldb,
    int nslab, int kw0, int mbase, int nbase, int g, int tg, float (*acc)[NJ][4])
{
    #pragma unroll 1
    for (int s = 0; s < nslab; s++) {
        const int kk = s * 8;
        uint32_t a[MI][4];
        #pragma unroll
        for (int i = 0; i < MI; i++) {
            int r0 = mbase + i * 16 + g;
            float f0 = A[r0 * lda + kk + tg];
            float f1 = A[(r0 + 8) * lda + kk + tg];
            float f2 = A[r0 * lda + kk + tg + 4];
            float f3 = A[(r0 + 8) * lda + kk + tg + 4];
            a[i][0] = CVTA ? f2tf(f0) : __float_as_uint(f0);
            a[i][1] = CVTA ? f2tf(f1) : __float_as_uint(f1);
            a[i][2] = CVTA ? f2tf(f2) : __float_as_uint(f2);
            a[i][3] = CVTA ? f2tf(f3) : __float_as_uint(f3);
        }
        #pragma unroll
        for (int j = 0; j < NJ; j++) {
            int n0 = nbase + j * 8;
            float fb0 = B[(kw0 + kk + tg) * ldb + n0 + g];
            float fb1 = B[(kw0 + kk + tg + 4) * ldb + n0 + g];
            uint32_t b0 = CVTB ? f2tf(fb0) : __float_as_uint(fb0);
            uint32_t b1 = CVTB ? f2tf(fb1) : __float_as_uint(fb1);
            #pragma unroll
            for (int i = 0; i < MI; i++)
                mma8(acc[i][j], a[i][0], a[i][1], a[i][2], a[i][3], b0, b1);
        }
    }
}

// bf16-pair A in smem (lda in u32 words), tf32 B in smem
template<int MI, int NJ>
__device__ __forceinline__ void mma_block_bf16A(
    const uint32_t* __restrict__ Ap, int lda, const float* __restrict__ B, int ldb,
    int nslab, int mbase, int nbase, int g, int tg, float (*acc)[NJ][4])
{
    const int th = tg & 1;            // half within pair
    #pragma unroll 1
    for (int s = 0; s < nslab; s++) {
        const int kk = s * 8;
        const int cp = (kk >> 1) + (tg >> 1);   // pair index of col kk+tg
        uint32_t a[MI][4];
        #pragma unroll
        for (int i = 0; i < MI; i++) {
            int r0 = mbase + i * 16 + g;
            uint32_t u0 = Ap[r0 * lda + cp];
            uint32_t u1 = Ap[(r0 + 8) * lda + cp];
            uint32_t u2 = Ap[r0 * lda + cp + 2];
            uint32_t u3 = Ap[(r0 + 8) * lda + cp + 2];
            a[i][0] = th ? (u0 & 0xffff0000u) : (u0 << 16);
            a[i][1] = th ? (u1 & 0xffff0000u) : (u1 << 16);
            a[i][2] = th ? (u2 & 0xffff0000u) : (u2 << 16);
            a[i][3] = th ? (u3 & 0xffff0000u) : (u3 << 16);
        }
        #pragma unroll
        for (int j = 0; j < NJ; j++) {
            int n0 = nbase + j * 8;
            uint32_t b0 = __float_as_uint(B[(kk + tg) * ldb + n0 + g]);
            uint32_t b1 = __float_as_uint(B[(kk + tg + 4) * ldb + n0 + g]);
            #pragma unroll
            for (int i = 0; i < MI; i++)
                mma8(acc[i][j], a[i][0], a[i][1], a[i][2], a[i][3], b0, b1);
        }
    }
}

// ============================================================================
// Kernel 1: layer1, 512 threads, M=256 (4 nodes/tile), 8 quarter-K cp.async
// stages, W1 resident (tf32).  Epilogue -> g_m1p (bf16 pairs).
// smem: W1 256x132 (135168) | buf0 256x36 (36864) | buf1 (36864) |
//       ptr0 (2048) | ptr1 (2048) = 212992 B
// ============================================================================
__device__ __forceinline__ void e1_issue(float* buf, int hc, int node0,
    const float* const* ptab, const float* __restrict__ hE, int t)
{
    const int c8 = t & 7;            // 16B chunk within 128B quarter-row
    const int rb = t >> 3;           // 0..63
    #pragma unroll
    for (int k = 0; k < 4; k++) {
        int r = rb + 64 * k;
        char* dst = (char*)buf + r * 144 + c8 * 16;
        const char* src;
        if (hc < 4) {
            src = (const char*)(ptab[r]) + hc * 128 + c8 * 16;
        } else {
            int er = r & 63; er = er < KK ? er : KK - 1;
            int node = node0 + (r >> 6);
            src = (const char*)(hE + ((size_t)(node * KK + er)) * HH + (hc - 4) * 32) + c8 * 16;
        }
        cp16(dst, src);
    }
}

__global__ __launch_bounds__(512, 1) void k_edge1(
    const float* __restrict__ hV, const float* __restrict__ hE,
    const int* __restrict__ Eidx, const float* __restrict__ W1,
    const float* __restrict__ b1)
{
    extern __shared__ char smem[];
    uint32_t* sW   = (uint32_t*)smem;                       // 256 x 132 tf32
    float*    bufA = (float*)(smem + 135168);
    float*    bufB = (float*)(smem + 135168 + 36864);
    const float** sPtr0 = (const float**)(smem + 208896);
    const float** sPtr1 = (const float**)(smem + 210944);

    const int tid  = threadIdx.x;
    const int lane = tid & 31, wid = tid >> 5;
    const int g = lane >> 2, tg = lane & 3;
    const int wm = wid >> 2, wn = wid & 3;     // 4 (m64) x 4 (n32)

    for (int idx = tid; idx < 256 * 32; idx += 512) {
        int row = idx >> 5, c4 = idx & 31;
        float4 w = ((const float4*)W1)[idx];
        uint32_t* d = &sW[row * 132 + c4 * 4];
        d[0] = f2tf(w.x); d[1] = f2tf(w.y); d[2] = f2tf(w.z); d[3] = f2tf(w.w);
    }
    int p0 = blockIdx.x;
    if (p0 < NT4 && tid < 256) {
        int er = tid & 63, node = 4 * p0 + (tid >> 6);
        int nb = (er < KK) ? Eidx[node * KK + er] : 0;
        sPtr0[tid] = hV + ((size_t)((node >> 11) * NN + nb)) * HH;
    }
    __syncthreads();
    if (p0 < NT4) e1_issue(bufA, 0, 4 * p0, sPtr0, hE, tid);
    CP_COMMIT();

    int par = 0;
    for (int p = blockIdx.x; p < NT4; p += gridDim.x) {
        const int node0 = 4 * p;
        const int pn = p + (int)gridDim.x;
        const float* const* ptrCur  = par ? sPtr1 : sPtr0;
        const float**       ptrNext = par ? (const float**)sPtr0 : (const float**)sPtr1;
        float acc[4][4][4];
        #pragma unroll
        for (int i = 0; i < 4; i++)
            #pragma unroll
            for (int j = 0; j < 4; j++)
                #pragma unroll
                for (int q = 0; q < 4; q++) acc[i][j][q] = 0.0f;

        int nbv = 0;
        #pragma unroll 1
        for (int hc = 0; hc < 8; hc++) {
            float* nbuf = ((hc + 1) & 1) ? bufB : bufA;
            if (hc < 7)          e1_issue(nbuf, hc + 1, node0, ptrCur, hE, tid);
            else if (pn < NT4)   e1_issue(nbuf, 0, 4 * pn, ptrNext, hE, tid);
            CP_COMMIT();
            CP_WAIT1();
            __syncthreads();
            if (hc == 0 && pn < NT4 && tid < 256) {
                int er = tid & 63, node = 4 * pn + (tid >> 6);
                nbv = (er < KK) ? Eidx[node * KK + er] : 0;
            }
            if (hc == 1 && pn < NT4 && tid < 256) {
                int node = 4 * pn + (tid >> 6);
                ptrNext[tid] = hV + ((size_t)((node >> 11) * NN + nbv)) * HH;
            }
            mma_block<4, 4, true, false>((hc & 1) ? bufB : bufA, 36,
                                         (const float*)sW, 132, 4, hc * 32,
                                         wm * 64, wn * 32, g, tg, acc);
            __syncthreads();
        }

        #pragma unroll
        for (int j = 0; j < 4; j++) {
            const int col = wn * 32 + j * 8 + 2 * tg;
            const float bb0 = b1[col], bb1 = b1[col + 1];
            #pragma unroll
            for (int i = 0; i < 4; i++) {
                const int r0 = wm * 64 + i * 16 + g;
                const int er0 = r0 & 63, er1 = (r0 + 8) & 63;
                const int nd0 = node0 + (r0 >> 6), nd1 = node0 + ((r0 + 8) >> 6);
                float v0 = gelu_tanh(acc[i][j][0] + bb0);
                float v1 = gelu_tanh(acc[i][j][1] + bb1);
                float v2 = gelu_tanh(acc[i][j][2] + bb0);
                float v3 = gelu_tanh(acc[i][j][3] + bb1);
                if (er0 < KK)
                    g_m1p[((size_t)(nd0 * KK + er0)) * 64 + (col >> 1)] = bpack(v0, v1);
                if (er1 < KK)
                    g_m1p[((size_t)(nd1 * KK + er1)) * 64 + (col >> 1)] = bpack(v2, v3);
            }
        }
        par ^= 1;
    }
}

// ============================================================================
// Kernel 2: layers 2+3 fused, 512 threads, M=256 (4 nodes/tile).
// m1/m2 live as bf16 pairs in sAp (256x68 u32); prefetch next tile in two
// R[8] register batches hidden under layers 2/3.
// smem: W2 (67584) | W3 (67584) | sAp 256x68x4 (69632) | mask (1024) = 205824 B
// ============================================================================
__device__ __forceinline__ void e2_pre8(uint2 R[8], int p, int half, int wid, int lane)
{
    #pragma unroll
    for (int i = 0; i < 8; i++) {
        int r = wid + 16 * (half * 8 + i);
        int er = r & 63; er = er < KK ? er : KK - 1;
        int node = 4 * p + (r >> 6);
        R[i] = ((const uint2*)(g_m1p + ((size_t)(node * KK + er)) * 64))[lane];
    }
}

__global__ __launch_bounds__(512, 1) void k_edge2(
    const float* __restrict__ hV, const float* __restrict__ mask_att,
    const float* __restrict__ W2, const float* __restrict__ b2,
    const float* __restrict__ W3, const float* __restrict__ b3)
{
    extern __shared__ char smem[];
    uint32_t* sW2 = (uint32_t*)smem;
    uint32_t* sW3 = (uint32_t*)(smem + 67584);
    uint32_t* sAp = (uint32_t*)(smem + 135168);   // 256 x 68 bf16-pairs
    float*  sMask = (float*)(smem + 204800);      // 256

    const int tid  = threadIdx.x;
    const int lane = tid & 31, wid = tid >> 5;
    const int g = lane >> 2, tg = lane & 3;
    const int wm = wid >> 2, wn = wid & 3;

    for (int idx = tid; idx < 128 * 32; idx += 512) {
        int row = idx >> 5, c4 = idx & 31;
        float4 w2 = ((const float4*)W2)[idx];
        float4 w3 = ((const float4*)W3)[idx];
        uint32_t* d2 = &sW2[row * 132 + c4 * 4];
        uint32_t* d3 = &sW3[row * 132 + c4 * 4];
        d2[0] = f2tf(w2.x); d2[1] = f2tf(w2.y); d2[2] = f2tf(w2.z); d2[3] = f2tf(w2.w);
        d3[0] = f2tf(w3.x); d3[1] = f2tf(w3.y); d3[2] = f2tf(w3.z); d3[3] = f2tf(w3.w);
    }

    uint2 R1[8], R2[8];
    float mreg = 0.0f;
    if (blockIdx.x < NT4) {
        e2_pre8(R1, blockIdx.x, 0, wid, lane);
        e2_pre8(R2, blockIdx.x, 1, wid, lane);
        if (tid < 256) {
            int er = tid & 63, node = 4 * blockIdx.x + (tid >> 6);
            mreg = (er < KK) ? mask_att[node * KK + er] : 0.0f;
        }
    }

    for (int p = blockIdx.x; p < NT4; p += gridDim.x) {
        const int node0 = 4 * p;
        const int pn = p + (int)gridDim.x;

        __syncthreads();   // prev tile layer-3 reads of sAp done
        #pragma unroll
        for (int i = 0; i < 8; i++) {
            int r = wid + 16 * i;
            ((uint2*)(sAp + r * 68))[lane] = R1[i];
        }
        #pragma unroll
        for (int i = 0; i < 8; i++) {
            int r = wid + 16 * (8 + i);
            ((uint2*)(sAp + r * 68))[lane] = R2[i];
        }
        if (tid < 256) sMask[tid] = mreg;
        __syncthreads();

        // prefetch first half of next tile (hides under layer 2)
        if (pn < NT4) {
            e2_pre8(R1, pn, 0, wid, lane);
            if (tid < 256) {
                int er = tid & 63, node = 4 * pn + (tid >> 6);
                mreg = (er < KK) ? mask_att[node * KK + er] : 0.0f;
            }
        }

        // ---- layer 2 ----
        float acc[4][4][4];
        #pragma unroll
        for (int i = 0; i < 4; i++)
            #pragma unroll
            for (int j = 0; j < 4; j++)
                #pragma unroll
                for (int q = 0; q < 4; q++) acc[i][j][q] = 0.0f;
        mma_block_bf16A<4, 4>(sAp, 68, (const float*)sW2, 132, 16,
                              wm * 64, wn * 32, g, tg, acc);
        __syncthreads();   // all layer-2 reads of sAp done

        // m2 = gelu(acc + b2) -> sAp (bf16 pairs)
        #pragma unroll
        for (int j = 0; j < 4; j++) {
            const int col = wn * 32 + j * 8 + 2 * tg;
            const int cp = col >> 1;
            const float bb0 = b2[col], bb1 = b2[col + 1];
            #pragma unroll
            for (int i = 0; i < 4; i++) {
                const int r0 = wm * 64 + i * 16 + g;
                sAp[r0 * 68 + cp]       = bpack(gelu_tanh(acc[i][j][0] + bb0),
                                                gelu_tanh(acc[i][j][1] + bb1));
                sAp[(r0 + 8) * 68 + cp] = bpack(gelu_tanh(acc[i][j][2] + bb0),
                                                gelu_tanh(acc[i][j][3] + bb1));
            }
        }
        // prefetch second half of next tile (hides under layer 3)
        if (pn < NT4) e2_pre8(R2, pn, 1, wid, lane);
        __syncthreads();   // m2 visible

        // ---- layer 3 ----
        #pragma unroll
        for (int i = 0; i < 4; i++)
            #pragma unroll
            for (int j = 0; j < 4; j++)
                #pragma unroll
                for (int q = 0; q < 4; q++) acc[i][j][q] = 0.0f;
        mma_block_bf16A<4, 4>(sAp, 68, (const float*)sW3, 132, 16,
                              wm * 64, wn * 32, g, tg, acc);

        // ---- mask + reduce over K (warp wm owns node node0+wm) ----
        const int node = node0 + wm;
        #pragma unroll
        for (int j = 0; j < 4; j++) {
            const int col = wn * 32 + j * 8 + 2 * tg;
            const float bb0 = b3[col], bb1 = b3[col + 1];
            float s0 = 0.f, s1 = 0.f;
            #pragma unroll
            for (int i = 0; i < 4; i++) {
                const int r0 = wm * 64 + i * 16 + g;
                const float m0 = sMask[r0], m8 = sMask[r0 + 8];
                s0 += m0 * (acc[i][j][0] + bb0) + m8 * (acc[i][j][2] + bb0);
                s1 += m0 * (acc[i][j][1] + bb1) + m8 * (acc[i][j][3] + bb1);
            }
            #pragma unroll
            for (int m = 4; m <= 16; m <<= 1) {
                s0 += __shfl_xor_sync(0xffffffffu, s0, m);
                s1 += __shfl_xor_sync(0xffffffffu, s1, m);
            }
            if (lane < 4) {
                const size_t base = (size_t)node * HH + col;
                g_h[base]     = hV[base]     + s0 * SCALE_INV;
                g_h[base + 1] = hV[base + 1] + s1 * SCALE_INV;
            }
        }
    }
}

// ============================================================================
// Kernel 3: FFN layer 1 (unchanged). CTA 128x256, grid 128, block 512.
// smem: sW 128x260 (133120) | sA 128x132 (67584) = 200704 B
// ============================================================================
__global__ __launch_bounds__(512, 1) void k_ff1(
    const float* __restrict__ Win, const float* __restrict__ bin)
{
    extern __shared__ char smem[];
    uint32_t* sW = (uint32_t*)smem;
    uint32_t* sA = (uint32_t*)(smem + 133120);

    const int tid  = threadIdx.x;
    const int lane = tid & 31, wid = tid >> 5;
    const int g = lane >> 2, tg = lane & 3;
    const int wm = wid >> 2, wn = wid & 3;
    const int mblk = blockIdx.x >> 1;
    const int nh   = (blockIdx.x & 1) * 256;

    for (int idx = tid; idx < 128 * 64; idx += 512) {
        int row = idx >> 6, c4 = idx & 63;
        float4 w = *(const float4*)(Win + (size_t)row * FFW + nh + c4 * 4);
        uint32_t* d = &sW[row * 260 + c4 * 4];
        d[0] = f2tf(w.x); d[1] = f2tf(w.y); d[2] = f2tf(w.z); d[3] = f2tf(w.w);
    }
    for (int idx = tid; idx < 128 * 32; idx += 512) {
        int row = idx >> 5, c4 = idx & 31;
        float4 v = *(const float4*)(g_h + (size_t)(mblk * 128 + row) * HH + c4 * 4);
        uint32_t* d = &sA[row * 132 + c4 * 4];
        d[0] = f2tf(v.x); d[1] = f2tf(v.y); d[2] = f2tf(v.z); d[3] = f2tf(v.w);
    }
    __syncthreads();

    float acc[2][8][4];
    #pragma unroll
    for (int i = 0; i < 2; i++)
        #pragma unroll
        for (int j = 0; j < 8; j++)
            #pragma unroll
            for (int q = 0; q < 4; q++) acc[i][j][q] = 0.0f;

    mma_block<2, 8, false, false>((const float*)sA, 132, (const float*)sW, 260,
                                  16, 0, wm * 32, wn * 64, g, tg, acc);

    #pragma unroll
    for (int j = 0; j < 8; j++) {
        const int col = wn * 64 + j * 8 + 2 * tg;
        const int ng = nh + col;
        const float bb0 = bin[ng], bb1 = bin[ng + 1];
        #pragma unroll
        for (int i = 0; i < 2; i++) {
            const int row = mblk * 128 + wm * 32 + i * 16 + g;
            float2* d0 = (float2*)(g_t + (size_t)row * FFW + ng);
            float2* d1 = (float2*)(g_t + (size_t)(row + 8) * FFW + ng);
            *d0 = make_float2(gelu_erf(acc[i][j][0] + bb0), gelu_erf(acc[i][j][1] + bb1));
            *d1 = make_float2(gelu_erf(acc[i][j][2] + bb0), gelu_erf(acc[i][j][3] + bb1));
        }
    }
}

// ============================================================================
// Kernel 4: FFN layer 2 (unchanged). 4 pipelined k-chunks.
// smem = 202752 B
// ============================================================================
__device__ __forceinline__ void ff2_issue(float* wbuf, float* abuf, int c, int mblk,
    const float* __restrict__ Wout, const float* __restrict__ gt, int t)
{
    {
        int r = t >> 1, half = t & 1;
        char* dst = (char*)wbuf + r * 528 + half * 256;
        const char* src = (const char*)(Wout + ((size_t)(c * 128 + r)) * HH + half * 64);
        #pragma unroll
        for (int s = 0; s < 16; s++) cp16(dst + s * 16, src + s * 16);
    }
    {
        int r = t >> 2, q = t & 3;
        char* dst = (char*)abuf + r * 528 + q * 128;
        const char* src = (const char*)(gt + ((size_t)(mblk * 64 + r)) * FFW + c * 128 + q * 32);
        #pragma unroll
        for (int s = 0; s < 8; s++) cp16(dst + s * 16, src + s * 16);
    }
}

__global__ __launch_bounds__(256, 1) void k_ff2(
    const float* __restrict__ Wout, const float* __restrict__ bout,
    const float* __restrict__ maskV, float* __restrict__ out)
{
    extern __shared__ char smem[];
    float* sW0 = (float*)smem;
    float* sW1 = (float*)(smem + 67584);
    float* sA0 = (float*)(smem + 135168);
    float* sA1 = (float*)(smem + 168960);

    const int tid  = threadIdx.x;
    const int lane = tid & 31, wid = tid >> 5;
    const int g = lane >> 2, tg = lane & 3;
    const int wm = wid >> 2, wn = wid & 3;
    const int mblk = blockIdx.x;

    ff2_issue(sW0, sA0, 0, mblk, Wout, g_t, tid);
    CP_COMMIT();

    float acc[2][4][4];
    #pragma unroll
    for (int i = 0; i < 2; i++)
        #pragma unroll
        for (int j = 0; j < 4; j++)
            #pragma unroll
            for (int q = 0; q < 4; q++) acc[i][j][q] = 0.0f;

    #pragma unroll 1
    for (int c = 0; c < 4; c++) {
        if (c < 3) {
            float* wb = ((c + 1) & 1) ? sW1 : sW0;
            float* ab = ((c + 1) & 1) ? sA1 : sA0;
            ff2_issue(wb, ab, c + 1, mblk, Wout, g_t, tid);
        }
        CP_COMMIT();
        CP_WAIT1();
        __syncthreads();
        mma_block<2, 4, true, true>((c & 1) ? sA1 : sA0, 132,
                                    (c & 1) ? sW1 : sW0, 132, 16, 0,
                                    wm * 32, wn * 32, g, tg, acc);
        __syncthreads();
    }

    #pragma unroll
    for (int j = 0; j < 4; j++) {
        const int col = wn * 32 + j * 8 + 2 * tg;
        const float bb0 = bout[col], bb1 = bout[col + 1];
        #pragma unroll
        for (int i = 0; i < 2; i++) {
            const int row0 = mblk * 64 + wm * 32 + i * 16 + g;
            #pragma unroll
            for (int h = 0; h < 2; h++) {
                const int row = row0 + h * 8;
                const float mv = maskV[row];
                const size_t base = (size_t)row * HH + col;
                float v0 = acc[i][j][h * 2 + 0] + bb0 + g_h[base];
                float v1 = acc[i][j][h * 2 + 1] + bb1 + g_h[base + 1];
                float2* d = (float2*)(out + base);
                *d = make_float2(mv * v0, mv * v1);
            }
        }
    }
}

// ============================================================================
extern "C" void kernel_launch(void* const* d_in, const int* in_sizes, int n_in,
                              void* d_out, int out_size)
{
    const float* hV    = (const float*)d_in[0];
    const float* hE    = (const float*)d_in[1];
    const int*   Eidx  = (const int*)  d_in[2];
    const float* maskV = (const float*)d_in[3];
    const float* maskA = (const float*)d_in[4];
    const float* W1    = (const float*)d_in[5];
    const float* b1    = (const float*)d_in[6];
    const float* W2    = (const float*)d_in[7];
    const float* b2    = (const float*)d_in[8];
    const float* W3    = (const float*)d_in[9];
    const float* b3    = (const float*)d_in[10];
    const float* Win   = (const float*)d_in[11];
    const float* bin   = (const float*)d_in[12];
    const float* Wout  = (const float*)d_in[13];
    const float* bout  = (const float*)d_in[14];
    float* out = (float*)d_out;

    const int smE1 = 212992;
    const int smE2 = 205824;
    const int smF1 = 200704;
    const int smF2 = 202752;

    cudaFuncSetAttribute(k_edge1, cudaFuncAttributeMaxDynamicSharedMemorySize, smE1);
    cudaFuncSetAttribute(k_edge2, cudaFuncAttributeMaxDynamicSharedMemorySize, smE2);
    cudaFuncSetAttribute(k_ff1,   cudaFuncAttributeMaxDynamicSharedMemorySize, smF1);
    cudaFuncSetAttribute(k_ff2,   cudaFuncAttributeMaxDynamicSharedMemorySize, smF2);

    k_edge1<<<152, 512, smE1>>>(hV, hE, Eidx, W1, b1);
    k_edge2<<<152, 512, smE2>>>(hV, maskA, W2, b2, W3, b3);
    k_ff1  <<<128, 512, smF1>>>(Win, bin);
    k_ff2  <<<128, 256, smF2>>>(Wout, bout, maskV, out);
}

// round 13
// speedup vs baseline: 2.1069x; 1.2930x over previous
#include <cuda_runtime.h>
#include <cstdint>
#include <math.h>

#define NN 2048
#define KK 48
#define HH 128
#define NODES 8192
#define FFW 512
#define NT4 2048               // NODES/4 (edge tiles, 4 nodes, M=192 real rows)
#define SCALE_INV (1.0f/30.0f)

// Bank rule (u32 words, mod 32): LD % 32 == 4 -> conflict-free A-frags (4g+tg)
// and B-frags (4tg+g). Buffers: 36 (quarter-K rows), 68 (bf16-pair rows),
// 132 (full-k f32/tf32), 260 (ff1 weight tile).

// -------- scratch --------
__device__ uint32_t g_m1p[(size_t)NODES * KK * 64];   // bf16 pairs
__device__ float    g_h [(size_t)NODES * HH];
__device__ float    g_t [(size_t)NODES * FFW];

// -------- helpers --------
__device__ __forceinline__ uint32_t f2tf(float x) {
    uint32_t u;
    asm("cvt.rna.tf32.f32 %0, %1;" : "=r"(u) : "f"(x));
    return u;
}
__device__ __forceinline__ uint32_t bpack(float lo, float hi) {  // [31:16]=hi,[15:0]=lo
    uint32_t r;
    asm("cvt.rn.bf16x2.f32 %0, %1, %2;" : "=r"(r) : "f"(hi), "f"(lo));
    return r;
}
__device__ __forceinline__ void cp16(void* s, const void* g) {
    uint32_t sa = (uint32_t)__cvta_generic_to_shared(s);
    asm volatile("cp.async.cg.shared.global [%0], [%1], 16;" :: "r"(sa), "l"(g));
}
#define CP_COMMIT() asm volatile("cp.async.commit_group;")
#define CP_WAIT1()  asm volatile("cp.async.wait_group 1;" ::: "memory")

__device__ __forceinline__ void mma8(float c[4],
                                     uint32_t a0, uint32_t a1, uint32_t a2, uint32_t a3,
                                     uint32_t b0, uint32_t b1) {
    asm volatile(
        "mma.sync.aligned.m16n8k8.row.col.f32.tf32.tf32.f32 "
        "{%0,%1,%2,%3},{%4,%5,%6,%7},{%8,%9},{%0,%1,%2,%3};"
        : "+f"(c[0]), "+f"(c[1]), "+f"(c[2]), "+f"(c[3])
        : "r"(a0), "r"(a1), "r"(a2), "r"(a3), "r"(b0), "r"(b1));
}

__device__ __forceinline__ float gelu_tanh(float x) {
    float x3 = x * x * x;
    return 0.5f * x * (1.0f + tanhf(0.7978845608028654f * (x + 0.044715f * x3)));
}
__device__ __forceinline__ float gelu_erf(float x) {
    return 0.5f * x * (1.0f + erff(x * 0.7071067811865476f));
}

// f32/tf32-in-smem A, tf32-in-smem B
template<int MI, int NJ, bool CVTA, bool CVTB>
__device__ __forceinline__ void mma_block(
    const float* __restrict__ A, int lda, const float* __restrict__ B, int ldb,
    int nslab, int kw0, int mbase, int nbase, int g, int tg, float (*acc)[NJ][4])
{
    #pragma unroll 1
    for (int s = 0; s < nslab; s++) {
        const int kk = s * 8;
        uint32_t a[MI][4];
        #pragma unroll
        for (int i = 0; i < MI; i++) {
            int r0 = mbase + i * 16 + g;
            float f0 = A[r0 * lda + kk + tg];
            float f1 = A[(r0 + 8) * lda + kk + tg];
            float f2 = A[r0 * lda + kk + tg + 4];
            float f3 = A[(r0 + 8) * lda + kk + tg + 4];
            a[i][0] = CVTA ? f2tf(f0) : __float_as_uint(f0);
            a[i][1] = CVTA ? f2tf(f1) : __float_as_uint(f1);
            a[i][2] = CVTA ? f2tf(f2) : __float_as_uint(f2);
            a[i][3] = CVTA ? f2tf(f3) : __float_as_uint(f3);
        }
        #pragma unroll
        for (int j = 0; j < NJ; j++) {
            int n0 = nbase + j * 8;
            float fb0 = B[(kw0 + kk + tg) * ldb + n0 + g];
            float fb1 = B[(kw0 + kk + tg + 4) * ldb + n0 + g];
            uint32_t b0 = CVTB ? f2tf(fb0) : __float_as_uint(fb0);
            uint32_t b1 = CVTB ? f2tf(fb1) : __float_as_uint(fb1);
            #pragma unroll
            for (int i = 0; i < MI; i++)
                mma8(acc[i][j], a[i][0], a[i][1], a[i][2], a[i][3], b0, b1);
        }
    }
}

// bf16-pair A in smem (lda in u32 words), tf32 B in smem
template<int MI, int NJ>
__device__ __forceinline__ void mma_block_bf16A(
    const uint32_t* __restrict__ Ap, int lda, const float* __restrict__ B, int ldb,
    int nslab, int mbase, int nbase, int g, int tg, float (*acc)[NJ][4])
{
    const int th = tg & 1;            // half within pair
    #pragma unroll 1
    for (int s = 0; s < nslab; s++) {
        const int kk = s * 8;
        const int cp = (kk >> 1) + (tg >> 1);   // pair index of col kk+tg
        uint32_t a[MI][4];
        #pragma unroll
        for (int i = 0; i < MI; i++) {
            int r0 = mbase + i * 16 + g;
            uint32_t u0 = Ap[r0 * lda + cp];
            uint32_t u1 = Ap[(r0 + 8) * lda + cp];
            uint32_t u2 = Ap[r0 * lda + cp + 2];
            uint32_t u3 = Ap[(r0 + 8) * lda + cp + 2];
            a[i][0] = th ? (u0 & 0xffff0000u) : (u0 << 16);
            a[i][1] = th ? (u1 & 0xffff0000u) : (u1 << 16);
            a[i][2] = th ? (u2 & 0xffff0000u) : (u2 << 16);
            a[i][3] = th ? (u3 & 0xffff0000u) : (u3 << 16);
        }
        #pragma unroll
        for (int j = 0; j < NJ; j++) {
            int n0 = nbase + j * 8;
            uint32_t b0 = __float_as_uint(B[(kk + tg) * ldb + n0 + g]);
            uint32_t b1 = __float_as_uint(B[(kk + tg + 4) * ldb + n0 + g]);
            #pragma unroll
            for (int i = 0; i < MI; i++)
                mma8(acc[i][j], a[i][0], a[i][1], a[i][2], a[i][3], b0, b1);
        }
    }
}

// ============================================================================
// Kernel 1: layer1, 512 threads, M=192 (4 nodes x 48 real edges, NO pad rows),
// 8 quarter-K cp.async stages, W1 resident (tf32). Epilogue -> g_m1p.
// smem: W1 256x132 (135168) | buf0 192x36 (27648) | buf1 (27648) |
//       ptr0 (1536) | ptr1 (1536) = 193536 B
// ============================================================================
__device__ __forceinline__ void e1_issue(float* buf, int hc, int node0,
    const float* const* ptab, const float* __restrict__ hE, int t)
{
    const int c8 = t & 7;            // 16B chunk within 128B quarter-row
    const int rb = t >> 3;           // 0..63
    #pragma unroll
    for (int k = 0; k < 3; k++) {
        int r = rb + 64 * k;         // 0..191
        char* dst = (char*)buf + r * 144 + c8 * 16;
        const char* src;
        if (hc < 4) {
            src = (const char*)(ptab[r]) + hc * 128 + c8 * 16;
        } else {
            int er = r % KK, node = node0 + r / KK;
            src = (const char*)(hE + ((size_t)(node * KK + er)) * HH + (hc - 4) * 32) + c8 * 16;
        }
        cp16(dst, src);
    }
}

__global__ __launch_bounds__(512, 1) void k_edge1(
    const float* __restrict__ hV, const float* __restrict__ hE,
    const int* __restrict__ Eidx, const float* __restrict__ W1,
    const float* __restrict__ b1)
{
    extern __shared__ char smem[];
    uint32_t* sW   = (uint32_t*)smem;                       // 256 x 132 tf32
    float*    bufA = (float*)(smem + 135168);
    float*    bufB = (float*)(smem + 162816);
    const float** sPtr0 = (const float**)(smem + 190464);
    const float** sPtr1 = (const float**)(smem + 192000);

    const int tid  = threadIdx.x;
    const int lane = tid & 31, wid = tid >> 5;
    const int g = lane >> 2, tg = lane & 3;
    const int wm = wid >> 2, wn = wid & 3;     // 4 (m48) x 4 (n32)

    for (int idx = tid; idx < 256 * 32; idx += 512) {
        int row = idx >> 5, c4 = idx & 31;
        float4 w = ((const float4*)W1)[idx];
        uint32_t* d = &sW[row * 132 + c4 * 4];
        d[0] = f2tf(w.x); d[1] = f2tf(w.y); d[2] = f2tf(w.z); d[3] = f2tf(w.w);
    }
    int p0 = blockIdx.x;
    if (p0 < NT4 && tid < 192) {
        int er = tid % KK, node = 4 * p0 + tid / KK;
        int nb = Eidx[node * KK + er];
        sPtr0[tid] = hV + ((size_t)((node >> 11) * NN + nb)) * HH;
    }
    __syncthreads();
    if (p0 < NT4) e1_issue(bufA, 0, 4 * p0, sPtr0, hE, tid);
    CP_COMMIT();

    int par = 0;
    for (int p = blockIdx.x; p < NT4; p += gridDim.x) {
        const int node0 = 4 * p;
        const int pn = p + (int)gridDim.x;
        const float* const* ptrCur  = par ? sPtr1 : sPtr0;
        const float**       ptrNext = par ? (const float**)sPtr0 : (const float**)sPtr1;
        float acc[3][4][4];
        #pragma unroll
        for (int i = 0; i < 3; i++)
            #pragma unroll
            for (int j = 0; j < 4; j++)
                #pragma unroll
                for (int q = 0; q < 4; q++) acc[i][j][q] = 0.0f;

        int nbv = 0;
        #pragma unroll 1
        for (int hc = 0; hc < 8; hc++) {
            float* nbuf = ((hc + 1) & 1) ? bufB : bufA;
            if (hc < 7)          e1_issue(nbuf, hc + 1, node0, ptrCur, hE, tid);
            else if (pn < NT4)   e1_issue(nbuf, 0, 4 * pn, ptrNext, hE, tid);
            CP_COMMIT();
            CP_WAIT1();
            __syncthreads();
            if (hc == 0 && pn < NT4 && tid < 192) {
                int er = tid % KK, node = 4 * pn + tid / KK;
                nbv = Eidx[node * KK + er];
            }
            if (hc == 1 && pn < NT4 && tid < 192) {
                int node = 4 * pn + tid / KK;
                ptrNext[tid] = hV + ((size_t)((node >> 11) * NN + nbv)) * HH;
            }
            mma_block<3, 4, true, false>((hc & 1) ? bufB : bufA, 36,
                                         (const float*)sW, 132, 4, hc * 32,
                                         wm * 48, wn * 32, g, tg, acc);
            __syncthreads();
        }

        // epilogue: all rows real (warp wm = node node0+wm, er = i*16+g[+8])
        const int nd = node0 + wm;
        #pragma unroll
        for (int j = 0; j < 4; j++) {
            const int col = wn * 32 + j * 8 + 2 * tg;
            const int cp = col >> 1;
            const float bb0 = b1[col], bb1 = b1[col + 1];
            #pragma unroll
            for (int i = 0; i < 3; i++) {
                const int er0 = i * 16 + g;
                g_m1p[((size_t)(nd * KK + er0)) * 64 + cp] =
                    bpack(gelu_tanh(acc[i][j][0] + bb0), gelu_tanh(acc[i][j][1] + bb1));
                g_m1p[((size_t)(nd * KK + er0 + 8)) * 64 + cp] =
                    bpack(gelu_tanh(acc[i][j][2] + bb0), gelu_tanh(acc[i][j][3] + bb1));
            }
        }
        par ^= 1;
    }
}

// ============================================================================
// Kernel 2: layers 2+3 fused, 512 threads, M=192 (4 nodes, no pad).
// m1/m2 as bf16 pairs in sAp (192x68 u32); next tile prefetched in two
// register batches hidden under layers 2/3.
// smem: W2 (67584) | W3 (67584) | sAp 192x68x4 (52224) | mask (768) = 188160 B
// ============================================================================
__device__ __forceinline__ void e2_pre6(uint2 R[6], int p, int half, int wid, int lane)
{
    #pragma unroll
    for (int i = 0; i < 6; i++) {
        int r = wid + 16 * (half * 6 + i);   // 0..95 / 96..191
        int er = r % KK, node = 4 * p + r / KK;
        R[i] = ((const uint2*)(g_m1p + ((size_t)(node * KK + er)) * 64))[lane];
    }
}

__global__ __launch_bounds__(512, 1) void k_edge2(
    const float* __restrict__ hV, const float* __restrict__ mask_att,
    const float* __restrict__ W2, const float* __restrict__ b2,
    const float* __restrict__ W3, const float* __restrict__ b3)
{
    extern __shared__ char smem[];
    uint32_t* sW2 = (uint32_t*)smem;
    uint32_t* sW3 = (uint32_t*)(smem + 67584);
    uint32_t* sAp = (uint32_t*)(smem + 135168);   // 192 x 68 bf16-pairs
    float*  sMask = (float*)(smem + 187392);      // 192

    const int tid  = threadIdx.x;
    const int lane = tid & 31, wid = tid >> 5;
    const int g = lane >> 2, tg = lane & 3;
    const int wm = wid >> 2, wn = wid & 3;

    for (int idx = tid; idx < 128 * 32; idx += 512) {
        int row = idx >> 5, c4 = idx & 31;
        float4 w2 = ((const float4*)W2)[idx];
        float4 w3 = ((const float4*)W3)[idx];
        uint32_t* d2 = &sW2[row * 132 + c4 * 4];
        uint32_t* d3 = &sW3[row * 132 + c4 * 4];
        d2[0] = f2tf(w2.x); d2[1] = f2tf(w2.y); d2[2] = f2tf(w2.z); d2[3] = f2tf(w2.w);
        d3[0] = f2tf(w3.x); d3[1] = f2tf(w3.y); d3[2] = f2tf(w3.z); d3[3] = f2tf(w3.w);
    }

    uint2 R1[6], R2[6];
    float mreg = 0.0f;
    if (blockIdx.x < NT4) {
        e2_pre6(R1, blockIdx.x, 0, wid, lane);
        e2_pre6(R2, blockIdx.x, 1, wid, lane);
        if (tid < 192) {
            int er = tid % KK, node = 4 * blockIdx.x + tid / KK;
            mreg = mask_att[node * KK + er];
        }
    }

    for (int p = blockIdx.x; p < NT4; p += gridDim.x) {
        const int node0 = 4 * p;
        const int pn = p + (int)gridDim.x;

        __syncthreads();   // prev tile layer-3 reads of sAp done
        #pragma unroll
        for (int i = 0; i < 6; i++) {
            int r = wid + 16 * i;
            ((uint2*)(sAp + r * 68))[lane] = R1[i];
        }
        #pragma unroll
        for (int i = 0; i < 6; i++) {
            int r = wid + 16 * (6 + i);
            ((uint2*)(sAp + r * 68))[lane] = R2[i];
        }
        if (tid < 192) sMask[tid] = mreg;
        __syncthreads();

        // prefetch first half of next tile (hides under layer 2)
        if (pn < NT4) {
            e2_pre6(R1, pn, 0, wid, lane);
            if (tid < 192) {
                int er = tid % KK, node = 4 * pn + tid / KK;
                mreg = mask_att[node * KK + er];
            }
        }

        // ---- layer 2 ----
        float acc[3][4][4];
        #pragma unroll
        for (int i = 0; i < 3; i++)
            #pragma unroll
            for (int j = 0; j < 4; j++)
                #pragma unroll
                for (int q = 0; q < 4; q++) acc[i][j][q] = 0.0f;
        mma_block_bf16A<3, 4>(sAp, 68, (const float*)sW2, 132, 16,
                              wm * 48, wn * 32, g, tg, acc);
        __syncthreads();   // all layer-2 reads of sAp done

        // m2 = gelu(acc + b2) -> sAp (bf16 pairs)
        #pragma unroll
        for (int j = 0; j < 4; j++) {
            const int col = wn * 32 + j * 8 + 2 * tg;
            const int cp = col >> 1;
            const float bb0 = b2[col], bb1 = b2[col + 1];
            #pragma unroll
            for (int i = 0; i < 3; i++) {
                const int r0 = wm * 48 + i * 16 + g;
                sAp[r0 * 68 + cp]       = bpack(gelu_tanh(acc[i][j][0] + bb0),
                                                gelu_tanh(acc[i][j][1] + bb1));
                sAp[(r0 + 8) * 68 + cp] = bpack(gelu_tanh(acc[i][j][2] + bb0),
                                                gelu_tanh(acc[i][j][3] + bb1));
            }
        }
        // prefetch second half of next tile (hides under layer 3)
        if (pn < NT4) e2_pre6(R2, pn, 1, wid, lane);
        __syncthreads();   // m2 visible

        // ---- layer 3 ----
        #pragma unroll
        for (int i = 0; i < 3; i++)
            #pragma unroll
            for (int j = 0; j < 4; j++)
                #pragma unroll
                for (int q = 0; q < 4; q++) acc[i][j][q] = 0.0f;
        mma_block_bf16A<3, 4>(sAp, 68, (const float*)sW3, 132, 16,
                              wm * 48, wn * 32, g, tg, acc);

        // ---- mask + reduce over K (warp wm owns node node0+wm; 48 rows) ----
        const int node = node0 + wm;
        #pragma unroll
        for (int j = 0; j < 4; j++) {
            const int col = wn * 32 + j * 8 + 2 * tg;
            const float bb0 = b3[col], bb1 = b3[col + 1];
            float s0 = 0.f, s1 = 0.f;
            #pragma unroll
            for (int i = 0; i < 3; i++) {
                const int r0 = wm * 48 + i * 16 + g;
                const float m0 = sMask[r0], m8 = sMask[r0 + 8];
                s0 += m0 * (acc[i][j][0] + bb0) + m8 * (acc[i][j][2] + bb0);
                s1 += m0 * (acc[i][j][1] + bb1) + m8 * (acc[i][j][3] + bb1);
            }
            #pragma unroll
            for (int m = 4; m <= 16; m <<= 1) {
                s0 += __shfl_xor_sync(0xffffffffu, s0, m);
                s1 += __shfl_xor_sync(0xffffffffu, s1, m);
            }
            if (lane < 4) {
                const size_t base = (size_t)node * HH + col;
                g_h[base]     = hV[base]     + s0 * SCALE_INV;
                g_h[base + 1] = hV[base + 1] + s1 * SCALE_INV;
            }
        }
    }
}

// ============================================================================
// Kernel 3: FFN layer 1 (unchanged). CTA 128x256, grid 128, block 512.
// smem: sW 128x260 (133120) | sA 128x132 (67584) = 200704 B
// ============================================================================
__global__ __launch_bounds__(512, 1) void k_ff1(
    const float* __restrict__ Win, const float* __restrict__ bin)
{
    extern __shared__ char smem[];
    uint32_t* sW = (uint32_t*)smem;
    uint32_t* sA = (uint32_t*)(smem + 133120);

    const int tid  = threadIdx.x;
    const int lane = tid & 31, wid = tid >> 5;
    const int g = lane >> 2, tg = lane & 3;
    const int wm = wid >> 2, wn = wid & 3;
    const int mblk = blockIdx.x >> 1;
    const int nh   = (blockIdx.x & 1) * 256;

    for (int idx = tid; idx < 128 * 64; idx += 512) {
        int row = idx >> 6, c4 = idx & 63;
        float4 w = *(const float4*)(Win + (size_t)row * FFW + nh + c4 * 4);
        uint32_t* d = &sW[row * 260 + c4 * 4];
        d[0] = f2tf(w.x); d[1] = f2tf(w.y); d[2] = f2tf(w.z); d[3] = f2tf(w.w);
    }
    for (int idx = tid; idx < 128 * 32; idx += 512) {
        int row = idx >> 5, c4 = idx & 31;
        float4 v = *(const float4*)(g_h + (size_t)(mblk * 128 + row) * HH + c4 * 4);
        uint32_t* d = &sA[row * 132 + c4 * 4];
        d[0] = f2tf(v.x); d[1] = f2tf(v.y); d[2] = f2tf(v.z); d[3] = f2tf(v.w);
    }
    __syncthreads();

    float acc[2][8][4];
    #pragma unroll
    for (int i = 0; i < 2; i++)
        #pragma unroll
        for (int j = 0; j < 8; j++)
            #pragma unroll
            for (int q = 0; q < 4; q++) acc[i][j][q] = 0.0f;

    mma_block<2, 8, false, false>((const float*)sA, 132, (const float*)sW, 260,
                                  16, 0, wm * 32, wn * 64, g, tg, acc);

    #pragma unroll
    for (int j = 0; j < 8; j++) {
        const int col = wn * 64 + j * 8 + 2 * tg;
        const int ng = nh + col;
        const float bb0 = bin[ng], bb1 = bin[ng + 1];
        #pragma unroll
        for (int i = 0; i < 2; i++) {
            const int row = mblk * 128 + wm * 32 + i * 16 + g;
            float2* d0 = (float2*)(g_t + (size_t)row * FFW + ng);
            float2* d1 = (float2*)(g_t + (size_t)(row + 8) * FFW + ng);
            *d0 = make_float2(gelu_erf(acc[i][j][0] + bb0), gelu_erf(acc[i][j][1] + bb1));
            *d1 = make_float2(gelu_erf(acc[i][j][2] + bb0), gelu_erf(acc[i][j][3] + bb1));
        }
    }
}

// ============================================================================
// Kernel 4: FFN layer 2 (unchanged). 4 pipelined k-chunks.  smem = 202752 B
// ============================================================================
__device__ __forceinline__ void ff2_issue(float* wbuf, float* abuf, int c, int mblk,
    const float* __restrict__ Wout, const float* __restrict__ gt, int t)
{
    {
        int r = t >> 1, half = t & 1;
        char* dst = (char*)wbuf + r * 528 + half * 256;
        const char* src = (const char*)(Wout + ((size_t)(c * 128 + r)) * HH + half * 64);
        #pragma unroll
        for (int s = 0; s < 16; s++) cp16(dst + s * 16, src + s * 16);
    }
    {
        int r = t >> 2, q = t & 3;
        char* dst = (char*)abuf + r * 528 + q * 128;
        const char* src = (const char*)(gt + ((size_t)(mblk * 64 + r)) * FFW + c * 128 + q * 32);
        #pragma unroll
        for (int s = 0; s < 8; s++) cp16(dst + s * 16, src + s * 16);
    }
}

__global__ __launch_bounds__(256, 1) void k_ff2(
    const float* __restrict__ Wout, const float* __restrict__ bout,
    const float* __restrict__ maskV, float* __restrict__ out)
{
    extern __shared__ char smem[];
    float* sW0 = (float*)smem;
    float* sW1 = (float*)(smem + 67584);
    float* sA0 = (float*)(smem + 135168);
    float* sA1 = (float*)(smem + 168960);

    const int tid  = threadIdx.x;
    const int lane = tid & 31, wid = tid >> 5;
    const int g = lane >> 2, tg = lane & 3;
    const int wm = wid >> 2, wn = wid & 3;
    const int mblk = blockIdx.x;

    ff2_issue(sW0, sA0, 0, mblk, Wout, g_t, tid);
    CP_COMMIT();

    float acc[2][4][4];
    #pragma unroll
    for (int i = 0; i < 2; i++)
        #pragma unroll
        for (int j = 0; j < 4; j++)
            #pragma unroll
            for (int q = 0; q < 4; q++) acc[i][j][q] = 0.0f;

    #pragma unroll 1
    for (int c = 0; c < 4; c++) {
        if (c < 3) {
            float* wb = ((c + 1) & 1) ? sW1 : sW0;
            float* ab = ((c + 1) & 1) ? sA1 : sA0;
            ff2_issue(wb, ab, c + 1, mblk, Wout, g_t, tid);
        }
        CP_COMMIT();
        CP_WAIT1();
        __syncthreads();
        mma_block<2, 4, true, true>((c & 1) ? sA1 : sA0, 132,
                                    (c & 1) ? sW1 : sW0, 132, 16, 0,
                                    wm * 32, wn * 32, g, tg, acc);
        __syncthreads();
    }

    #pragma unroll
    for (int j = 0; j < 4; j++) {
        const int col = wn * 32 + j * 8 + 2 * tg;
        const float bb0 = bout[col], bb1 = bout[col + 1];
        #pragma unroll
        for (int i = 0; i < 2; i++) {
            const int row0 = mblk * 64 + wm * 32 + i * 16 + g;
            #pragma unroll
            for (int h = 0; h < 2; h++) {
                const int row = row0 + h * 8;
                const float mv = maskV[row];
                const size_t base = (size_t)row * HH + col;
                float v0 = acc[i][j][h * 2 + 0] + bb0 + g_h[base];
                float v1 = acc[i][j][h * 2 + 1] + bb1 + g_h[base + 1];
                float2* d = (float2*)(out + base);
                *d = make_float2(mv * v0, mv * v1);
            }
        }
    }
}

// ============================================================================
extern "C" void kernel_launch(void* const* d_in, const int* in_sizes, int n_in,
                              void* d_out, int out_size)
{
    const float* hV    = (const float*)d_in[0];
    const float* hE    = (const float*)d_in[1];
    const int*   Eidx  = (const int*)  d_in[2];
    const float* maskV = (const float*)d_in[3];
    const float* maskA = (const float*)d_in[4];
    const float* W1    = (const float*)d_in[5];
    const float* b1    = (const float*)d_in[6];
    const float* W2    = (const float*)d_in[7];
    const float* b2    = (const float*)d_in[8];
    const float* W3    = (const float*)d_in[9];
    const float* b3    = (const float*)d_in[10];
    const float* Win   = (const float*)d_in[11];
    const float* bin   = (const float*)d_in[12];
    const float* Wout  = (const float*)d_in[13];
    const float* bout  = (const float*)d_in[14];
    float* out = (float*)d_out;

    const int smE1 = 193536;
    const int smE2 = 188160;
    const int smF1 = 200704;
    const int smF2 = 202752;

    cudaFuncSetAttribute(k_edge1, cudaFuncAttributeMaxDynamicSharedMemorySize, smE1);
    cudaFuncSetAttribute(k_edge2, cudaFuncAttributeMaxDynamicSharedMemorySize, smE2);
    cudaFuncSetAttribute(k_ff1,   cudaFuncAttributeMaxDynamicSharedMemorySize, smF1);
    cudaFuncSetAttribute(k_ff2,   cudaFuncAttributeMaxDynamicSharedMemorySize, smF2);

    k_edge1<<<152, 512, smE1>>>(hV, hE, Eidx, W1, b1);
    k_edge2<<<152, 512, smE2>>>(hV, maskA, W2, b2, W3, b3);
    k_ff1  <<<128, 512, smF1>>>(Win, bin);
    k_ff2  <<<128, 256, smF2>>>(Wout, bout, maskV, out);
}

// round 15
// speedup vs baseline: 2.4642x; 1.1695x over previous
#include <cuda_runtime.h>
#include <cstdint>
#include <math.h>

#define NN 2048
#define KK 48
#define HH 128
#define NODES 8192
#define FFW 512
#define NT4 2048               // NODES/4 (edge tiles, 4 nodes, M=192 real rows)
#define SCALE_INV (1.0f/30.0f)

// Bank rule (u32 words, mod 32): LD % 32 == 4 -> conflict-free A-frags (4g+tg)
// and B-frags (4tg+g). Buffers: 36 (quarter-K f32 rows), 68 (bf16-pair rows),
// 132 (weight-pair rows / full-k), 260 (ff1 weight tile).

// -------- scratch --------
__device__ uint32_t g_m1p[(size_t)NODES * KK * 64];   // bf16 pairs
__device__ float    g_h [(size_t)NODES * HH];
__device__ float    g_t [(size_t)NODES * FFW];

// -------- helpers --------
__device__ __forceinline__ uint32_t f2tf(float x) {
    uint32_t u;
    asm("cvt.rna.tf32.f32 %0, %1;" : "=r"(u) : "f"(x));
    return u;
}
__device__ __forceinline__ uint32_t bpack(float lo, float hi) {  // [31:16]=hi,[15:0]=lo
    uint32_t r;
    asm("cvt.rn.bf16x2.f32 %0, %1, %2;" : "=r"(r) : "f"(hi), "f"(lo));
    return r;
}
__device__ __forceinline__ void cp16(void* s, const void* g) {
    uint32_t sa = (uint32_t)__cvta_generic_to_shared(s);
    asm volatile("cp.async.cg.shared.global [%0], [%1], 16;" :: "r"(sa), "l"(g));
}
#define CP_COMMIT() asm volatile("cp.async.commit_group;")
#define CP_WAIT1()  asm volatile("cp.async.wait_group 1;" ::: "memory")

__device__ __forceinline__ void mma8(float c[4],
                                     uint32_t a0, uint32_t a1, uint32_t a2, uint32_t a3,
                                     uint32_t b0, uint32_t b1) {
    asm volatile(
        "mma.sync.aligned.m16n8k8.row.col.f32.tf32.tf32.f32 "
        "{%0,%1,%2,%3},{%4,%5,%6,%7},{%8,%9},{%0,%1,%2,%3};"
        : "+f"(c[0]), "+f"(c[1]), "+f"(c[2]), "+f"(c[3])
        : "r"(a0), "r"(a1), "r"(a2), "r"(a3), "r"(b0), "r"(b1));
}
__device__ __forceinline__ void mma16(float c[4],
                                      uint32_t a0, uint32_t a1, uint32_t a2, uint32_t a3,
                                      uint32_t b0, uint32_t b1) {
    asm volatile(
        "mma.sync.aligned.m16n8k16.row.col.f32.bf16.bf16.f32 "
        "{%0,%1,%2,%3},{%4,%5,%6,%7},{%8,%9},{%0,%1,%2,%3};"
        : "+f"(c[0]), "+f"(c[1]), "+f"(c[2]), "+f"(c[3])
        : "r"(a0), "r"(a1), "r"(a2), "r"(a3), "r"(b0), "r"(b1));
}

__device__ __forceinline__ float gelu_tanh(float x) {
    float x3 = x * x * x;
    return 0.5f * x * (1.0f + tanhf(0.7978845608028654f * (x + 0.044715f * x3)));
}
__device__ __forceinline__ float gelu_erf(float x) {
    return 0.5f * x * (1.0f + erff(x * 0.7071067811865476f));
}

// tf32 path (FFN kernels): f32/tf32-in-smem A, tf32-in-smem B
template<int MI, int NJ, bool CVTA, bool CVTB>
__device__ __forceinline__ void mma_block(
    const float* __restrict__ A, int lda, const float* __restrict__ B, int ldb,
    int nslab, int kw0, int mbase, int nbase, int g, int tg, float (*acc)[NJ][4])
{
    #pragma unroll 1
    for (int s = 0; s < nslab; s++) {
        const int kk = s * 8;
        uint32_t a[MI][4];
        #pragma unroll
        for (int i = 0; i < MI; i++) {
            int r0 = mbase + i * 16 + g;
            float f0 = A[r0 * lda + kk + tg];
            float f1 = A[(r0 + 8) * lda + kk + tg];
            float f2 = A[r0 * lda + kk + tg + 4];
            float f3 = A[(r0 + 8) * lda + kk + tg + 4];
            a[i][0] = CVTA ? f2tf(f0) : __float_as_uint(f0);
            a[i][1] = CVTA ? f2tf(f1) : __float_as_uint(f1);
            a[i][2] = CVTA ? f2tf(f2) : __float_as_uint(f2);
            a[i][3] = CVTA ? f2tf(f3) : __float_as_uint(f3);
        }
        #pragma unroll
        for (int j = 0; j < NJ; j++) {
            int n0 = nbase + j * 8;
            float fb0 = B[(kw0 + kk + tg) * ldb + n0 + g];
            float fb1 = B[(kw0 + kk + tg + 4) * ldb + n0 + g];
            uint32_t b0 = CVTB ? f2tf(fb0) : __float_as_uint(fb0);
            uint32_t b1 = CVTB ? f2tf(fb1) : __float_as_uint(fb1);
            #pragma unroll
            for (int i = 0; i < MI; i++)
                mma8(acc[i][j], a[i][0], a[i][1], a[i][2], a[i][3], b0, b1);
        }
    }
}

// bf16 mma, A as bf16 pairs in smem [row][kpair] (lda u32), B as bf16 pairs
// [kpair][n] (ldb u32).
template<int MI, int NJ>
__device__ __forceinline__ void mma_block_pp(
    const uint32_t* __restrict__ Ap, int lda, const uint32_t* __restrict__ Bp, int ldb,
    int nslab, int mbase, int nbase, int g, int tg, float (*acc)[NJ][4])
{
    #pragma unroll 1
    for (int s = 0; s < nslab; s++) {
        const int kp = s * 8;
        uint32_t a[MI][4];
        #pragma unroll
        for (int i = 0; i < MI; i++) {
            int r0 = mbase + i * 16 + g;
            a[i][0] = Ap[r0 * lda + kp + tg];
            a[i][1] = Ap[(r0 + 8) * lda + kp + tg];
            a[i][2] = Ap[r0 * lda + kp + tg + 4];
            a[i][3] = Ap[(r0 + 8) * lda + kp + tg + 4];
        }
        #pragma unroll
        for (int j = 0; j < NJ; j++) {
            int n0 = nbase + j * 8;
            uint32_t b0 = Bp[(kp + tg) * ldb + n0 + g];
            uint32_t b1 = Bp[(kp + tg + 4) * ldb + n0 + g];
            #pragma unroll
            for (int i = 0; i < MI; i++)
                mma16(acc[i][j], a[i][0], a[i][1], a[i][2], a[i][3], b0, b1);
        }
    }
}

// bf16 mma, A as f32 in smem (float2 load + pack), B as bf16 pairs [kpair][n].
template<int MI, int NJ>
__device__ __forceinline__ void mma_block_fp(
    const float* __restrict__ A, int lda, const uint32_t* __restrict__ Bp, int ldb,
    int nslab, int kpw0, int mbase, int nbase, int g, int tg, float (*acc)[NJ][4])
{
    #pragma unroll 1
    for (int s = 0; s < nslab; s++) {
        const int k0 = s * 16;
        const int kpw = kpw0 + s * 8;
        uint32_t a[MI][4];
        #pragma unroll
        for (int i = 0; i < MI; i++) {
            int r0 = mbase + i * 16 + g;
            float2 v0 = *(const float2*)(A + r0 * lda + k0 + 2 * tg);
            float2 v1 = *(const float2*)(A + (r0 + 8) * lda + k0 + 2 * tg);
            float2 v2 = *(const float2*)(A + r0 * lda + k0 + 2 * tg + 8);
            float2 v3 = *(const float2*)(A + (r0 + 8) * lda + k0 + 2 * tg + 8);
            a[i][0] = bpack(v0.x, v0.y);
            a[i][1] = bpack(v1.x, v1.y);
            a[i][2] = bpack(v2.x, v2.y);
            a[i][3] = bpack(v3.x, v3.y);
        }
        #pragma unroll
        for (int j = 0; j < NJ; j++) {
            int n0 = nbase + j * 8;
            uint32_t b0 = Bp[(kpw + tg) * ldb + n0 + g];
            uint32_t b1 = Bp[(kpw + tg + 4) * ldb + n0 + g];
            #pragma unroll
            for (int i = 0; i < MI; i++)
                mma16(acc[i][j], a[i][0], a[i][1], a[i][2], a[i][3], b0, b1);
        }
    }
}

// ============================================================================
// Kernel 1: layer1, bf16 mma, 512 threads, M=192 (no pad rows), 8 quarter-K
// cp.async f32 stages, W1 resident as bf16 pairs.  Epilogue -> g_m1p.
// smem: W1p 128x132 (67584) | buf0 192x36 (27648) | buf1 (27648) |
//       ptr0 (1536) | ptr1 (1536) = 125952 B
// ============================================================================
__device__ __forceinline__ void e1_issue(float* buf, int hc, int node0,
    const float* const* ptab, const float* __restrict__ hE, int t)
{
    const int c8 = t & 7;            // 16B chunk within 128B quarter-row
    const int rb = t >> 3;           // 0..63
    #pragma unroll
    for (int k = 0; k < 3; k++) {
        int r = rb + 64 * k;         // 0..191
        char* dst = (char*)buf + r * 144 + c8 * 16;
        const char* src;
        if (hc < 4) {
            src = (const char*)(ptab[r]) + hc * 128 + c8 * 16;
        } else {
            int er = r % KK, node = node0 + r / KK;
            src = (const char*)(hE + ((size_t)(node * KK + er)) * HH + (hc - 4) * 32) + c8 * 16;
        }
        cp16(dst, src);
    }
}

__global__ __launch_bounds__(512, 1) void k_edge1(
    const float* __restrict__ hV, const float* __restrict__ hE,
    const int* __restrict__ Eidx, const float* __restrict__ W1,
    const float* __restrict__ b1)
{
    extern __shared__ char smem[];
    uint32_t* sWp  = (uint32_t*)smem;                       // 128 x 132 bf16 pairs
    float*    bufA = (float*)(smem + 67584);
    float*    bufB = (float*)(smem + 95232);
    const float** sPtr0 = (const float**)(smem + 122880);
    const float** sPtr1 = (const float**)(smem + 124416);

    const int tid  = threadIdx.x;
    const int lane = tid & 31, wid = tid >> 5;
    const int g = lane >> 2, tg = lane & 3;
    const int wm = wid >> 2, wn = wid & 3;     // 4 (m48) x 4 (n32)

    // W1 (256x128) -> bf16 pairs [kpair][n]
    for (int idx = tid; idx < 128 * 32; idx += 512) {
        int kp = idx >> 5, c4 = idx & 31;
        float4 w0 = *(const float4*)(W1 + (size_t)(2 * kp) * HH + c4 * 4);
        float4 w1 = *(const float4*)(W1 + (size_t)(2 * kp + 1) * HH + c4 * 4);
        uint32_t* d = &sWp[kp * 132 + c4 * 4];
        d[0] = bpack(w0.x, w1.x); d[1] = bpack(w0.y, w1.y);
        d[2] = bpack(w0.z, w1.z); d[3] = bpack(w0.w, w1.w);
    }
    int p0 = blockIdx.x;
    if (p0 < NT4 && tid < 192) {
        int er = tid % KK, node = 4 * p0 + tid / KK;
        int nb = Eidx[node * KK + er];
        sPtr0[tid] = hV + ((size_t)((node >> 11) * NN + nb)) * HH;
    }
    __syncthreads();
    if (p0 < NT4) e1_issue(bufA, 0, 4 * p0, sPtr0, hE, tid);
    CP_COMMIT();

    int par = 0;
    for (int p = blockIdx.x; p < NT4; p += gridDim.x) {
        const int node0 = 4 * p;
        const int pn = p + (int)gridDim.x;
        const float* const* ptrCur  = par ? sPtr1 : sPtr0;
        const float**       ptrNext = par ? (const float**)sPtr0 : (const float**)sPtr1;
        float acc[3][4][4];
        #pragma unroll
        for (int i = 0; i < 3; i++)
            #pragma unroll
            for (int j = 0; j < 4; j++)
                #pragma unroll
                for (int q = 0; q < 4; q++) acc[i][j][q] = 0.0f;

        int nbv = 0;
        #pragma unroll 1
        for (int hc = 0; hc < 8; hc++) {
            float* nbuf = ((hc + 1) & 1) ? bufB : bufA;
            if (hc < 7)          e1_issue(nbuf, hc + 1, node0, ptrCur, hE, tid);
            else if (pn < NT4)   e1_issue(nbuf, 0, 4 * pn, ptrNext, hE, tid);
            CP_COMMIT();
            CP_WAIT1();
            __syncthreads();
            if (hc == 0 && pn < NT4 && tid < 192) {
                int er = tid % KK, node = 4 * pn + tid / KK;
                nbv = Eidx[node * KK + er];
            }
            if (hc == 1 && pn < NT4 && tid < 192) {
                int node = 4 * pn + tid / KK;
                ptrNext[tid] = hV + ((size_t)((node >> 11) * NN + nbv)) * HH;
            }
            mma_block_fp<3, 4>((hc & 1) ? bufB : bufA, 36, sWp, 132,
                               2, hc * 16, wm * 48, wn * 32, g, tg, acc);
            __syncthreads();
        }

        // epilogue: warp wm = node node0+wm, er = i*16+g[+8]
        const int nd = node0 + wm;
        #pragma unroll
        for (int j = 0; j < 4; j++) {
            const int col = wn * 32 + j * 8 + 2 * tg;
            const int cp = col >> 1;
            const float bb0 = b1[col], bb1 = b1[col + 1];
            #pragma unroll
            for (int i = 0; i < 3; i++) {
                const int er0 = i * 16 + g;
                g_m1p[((size_t)(nd * KK + er0)) * 64 + cp] =
                    bpack(gelu_tanh(acc[i][j][0] + bb0), gelu_tanh(acc[i][j][1] + bb1));
                g_m1p[((size_t)(nd * KK + er0 + 8)) * 64 + cp] =
                    bpack(gelu_tanh(acc[i][j][2] + bb0), gelu_tanh(acc[i][j][3] + bb1));
            }
        }
        par ^= 1;
    }
}

// ============================================================================
// Kernel 2: layers 2+3 fused, bf16 mma throughout, 512 threads, M=192.
// m1/m2 as bf16 pairs in sAp (192x68); W2/W3 as bf16 pairs (64x132 each).
// smem: W2p (33792) | W3p (33792) | sAp (52224) | mask (768) = 120576 B
// ============================================================================
__device__ __forceinline__ void e2_pre6(uint2 R[6], int p, int half, int wid, int lane)
{
    #pragma unroll
    for (int i = 0; i < 6; i++) {
        int r = wid + 16 * (half * 6 + i);   // 0..95 / 96..191
        int er = r % KK, node = 4 * p + r / KK;
        R[i] = ((const uint2*)(g_m1p + ((size_t)(node * KK + er)) * 64))[lane];
    }
}

__global__ __launch_bounds__(512, 1) void k_edge2(
    const float* __restrict__ hV, const float* __restrict__ mask_att,
    const float* __restrict__ W2, const float* __restrict__ b2,
    const float* __restrict__ W3, const float* __restrict__ b3)
{
    extern __shared__ char smem[];
    uint32_t* sW2p = (uint32_t*)smem;             // 64 x 132 bf16 pairs
    uint32_t* sW3p = (uint32_t*)(smem + 33792);
    uint32_t* sAp  = (uint32_t*)(smem + 67584);   // 192 x 68 bf16 pairs
    float*   sMask = (float*)(smem + 119808);     // 192

    const int tid  = threadIdx.x;
    const int lane = tid & 31, wid = tid >> 5;
    const int g = lane >> 2, tg = lane & 3;
    const int wm = wid >> 2, wn = wid & 3;

    for (int idx = tid; idx < 64 * 32; idx += 512) {
        int kp = idx >> 5, c4 = idx & 31;
        float4 w20 = *(const float4*)(W2 + (size_t)(2 * kp) * HH + c4 * 4);
        float4 w21 = *(const float4*)(W2 + (size_t)(2 * kp + 1) * HH + c4 * 4);
        float4 w30 = *(const float4*)(W3 + (size_t)(2 * kp) * HH + c4 * 4);
        float4 w31 = *(const float4*)(W3 + (size_t)(2 * kp + 1) * HH + c4 * 4);
        uint32_t* d2 = &sW2p[kp * 132 + c4 * 4];
        uint32_t* d3 = &sW3p[kp * 132 + c4 * 4];
        d2[0] = bpack(w20.x, w21.x); d2[1] = bpack(w20.y, w21.y);
        d2[2] = bpack(w20.z, w21.z); d2[3] = bpack(w20.w, w21.w);
        d3[0] = bpack(w30.x, w31.x); d3[1] = bpack(w30.y, w31.y);
        d3[2] = bpack(w30.z, w31.z); d3[3] = bpack(w30.w, w31.w);
    }

    uint2 R1[6], R2[6];
    float mreg = 0.0f;
    if (blockIdx.x < NT4) {
        e2_pre6(R1, blockIdx.x, 0, wid, lane);
        e2_pre6(R2, blockIdx.x, 1, wid, lane);
        if (tid < 192) {
            int er = tid % KK, node = 4 * blockIdx.x + tid / KK;
            mreg = mask_att[node * KK + er];
        }
    }

    for (int p = blockIdx.x; p < NT4; p += gridDim.x) {
        const int node0 = 4 * p;
        const int pn = p + (int)gridDim.x;

        __syncthreads();   // prev tile layer-3 reads of sAp done
        #pragma unroll
        for (int i = 0; i < 6; i++) {
            int r = wid + 16 * i;
            ((uint2*)(sAp + r * 68))[lane] = R1[i];
        }
        #pragma unroll
        for (int i = 0; i < 6; i++) {
            int r = wid + 16 * (6 + i);
            ((uint2*)(sAp + r * 68))[lane] = R2[i];
        }
        if (tid < 192) sMask[tid] = mreg;
        __syncthreads();

        // prefetch first half of next tile (hides under layer 2)
        if (pn < NT4) {
            e2_pre6(R1, pn, 0, wid, lane);
            if (tid < 192) {
                int er = tid % KK, node = 4 * pn + tid / KK;
                mreg = mask_att[node * KK + er];
            }
        }

        // ---- layer 2 (bf16) ----
        float acc[3][4][4];
        #pragma unroll
        for (int i = 0; i < 3; i++)
            #pragma unroll
            for (int j = 0; j < 4; j++)
                #pragma unroll
                for (int q = 0; q < 4; q++) acc[i][j][q] = 0.0f;
        mma_block_pp<3, 4>(sAp, 68, sW2p, 132, 8,
                           wm * 48, wn * 32, g, tg, acc);
        __syncthreads();   // all layer-2 reads of sAp done

        // m2 = gelu(acc + b2) -> sAp (bf16 pairs)
        #pragma unroll
        for (int j = 0; j < 4; j++) {
            const int col = wn * 32 + j * 8 + 2 * tg;
            const int cp = col >> 1;
            const float bb0 = b2[col], bb1 = b2[col + 1];
            #pragma unroll
            for (int i = 0; i < 3; i++) {
                const int r0 = wm * 48 + i * 16 + g;
                sAp[r0 * 68 + cp]       = bpack(gelu_tanh(acc[i][j][0] + bb0),
                                                gelu_tanh(acc[i][j][1] + bb1));
                sAp[(r0 + 8) * 68 + cp] = bpack(gelu_tanh(acc[i][j][2] + bb0),
                                                gelu_tanh(acc[i][j][3] + bb1));
            }
        }
        // prefetch second half of next tile (hides under layer 3)
        if (pn < NT4) e2_pre6(R2, pn, 1, wid, lane);
        __syncthreads();   // m2 visible

        // ---- layer 3 (bf16) ----
        #pragma unroll
        for (int i = 0; i < 3; i++)
            #pragma unroll
            for (int j = 0; j < 4; j++)
                #pragma unroll
                for (int q = 0; q < 4; q++) acc[i][j][q] = 0.0f;
        mma_block_pp<3, 4>(sAp, 68, sW3p, 132, 8,
                           wm * 48, wn * 32, g, tg, acc);

        // ---- mask + reduce over K (warp wm owns node node0+wm; 48 rows) ----
        const int node = node0 + wm;
        #pragma unroll
        for (int j = 0; j < 4; j++) {
            const int col = wn * 32 + j * 8 + 2 * tg;
            const float bb0 = b3[col], bb1 = b3[col + 1];
            float s0 = 0.f, s1 = 0.f;
            #pragma unroll
            for (int i = 0; i < 3; i++) {
                const int r0 = wm * 48 + i * 16 + g;
                const float m0 = sMask[r0], m8 = sMask[r0 + 8];
                s0 += m0 * (acc[i][j][0] + bb0) + m8 * (acc[i][j][2] + bb0);
                s1 += m0 * (acc[i][j][1] + bb1) + m8 * (acc[i][j][3] + bb1);
            }
            #pragma unroll
            for (int m = 4; m <= 16; m <<= 1) {
                s0 += __shfl_xor_sync(0xffffffffu, s0, m);
                s1 += __shfl_xor_sync(0xffffffffu, s1, m);
            }
            if (lane < 4) {
                const size_t base = (size_t)node * HH + col;
                g_h[base]     = hV[base]     + s0 * SCALE_INV;
                g_h[base + 1] = hV[base + 1] + s1 * SCALE_INV;
            }
        }
    }
}

// ============================================================================
// Kernel 3: FFN layer 1 (unchanged, tf32). CTA 128x256, grid 128, block 512.
// smem: sW 128x260 (133120) | sA 128x132 (67584) = 200704 B
// ============================================================================
__global__ __launch_bounds__(512, 1) void k_ff1(
    const float* __restrict__ Win, const float* __restrict__ bin)
{
    extern __shared__ char smem[];
    uint32_t* sW = (uint32_t*)smem;
    uint32_t* sA = (uint32_t*)(smem + 133120);

    const int tid  = threadIdx.x;
    const int lane = tid & 31, wid = tid >> 5;
    const int g = lane >> 2, tg = lane & 3;
    const int wm = wid >> 2, wn = wid & 3;
    const int mblk = blockIdx.x >> 1;
    const int nh   = (blockIdx.x & 1) * 256;

    for (int idx = tid; idx < 128 * 64; idx += 512) {
        int row = idx >> 6, c4 = idx & 63;
        float4 w = *(const float4*)(Win + (size_t)row * FFW + nh + c4 * 4);
        uint32_t* d = &sW[row * 260 + c4 * 4];
        d[0] = f2tf(w.x); d[1] = f2tf(w.y); d[2] = f2tf(w.z); d[3] = f2tf(w.w);
    }
    for (int idx = tid; idx < 128 * 32; idx += 512) {
        int row = idx >> 5, c4 = idx & 31;
        float4 v = *(const float4*)(g_h + (size_t)(mblk * 128 + row) * HH + c4 * 4);
        uint32_t* d = &sA[row * 132 + c4 * 4];
        d[0] = f2tf(v.x); d[1] = f2tf(v.y); d[2] = f2tf(v.z); d[3] = f2tf(v.w);
    }
    __syncthreads();

    float acc[2][8][4];
    #pragma unroll
    for (int i = 0; i < 2; i++)
        #pragma unroll
        for (int j = 0; j < 8; j++)
            #pragma unroll
            for (int q = 0; q < 4; q++) acc[i][j][q] = 0.0f;

    mma_block<2, 8, false, false>((const float*)sA, 132, (const float*)sW, 260,
                                  16, 0, wm * 32, wn * 64, g, tg, acc);

    #pragma unroll
    for (int j = 0; j < 8; j++) {
        const int col = wn * 64 + j * 8 + 2 * tg;
        const int ng = nh + col;
        const float bb0 = bin[ng], bb1 = bin[ng + 1];
        #pragma unroll
        for (int i = 0; i < 2; i++) {
            const int row = mblk * 128 + wm * 32 + i * 16 + g;
            float2* d0 = (float2*)(g_t + (size_t)row * FFW + ng);
            float2* d1 = (float2*)(g_t + (size_t)(row + 8) * FFW + ng);
            *d0 = make_float2(gelu_erf(acc[i][j][0] + bb0), gelu_erf(acc[i][j][1] + bb1));
            *d1 = make_float2(gelu_erf(acc[i][j][2] + bb0), gelu_erf(acc[i][j][3] + bb1));
        }
    }
}

// ============================================================================
// Kernel 4: FFN layer 2 (unchanged, tf32). 4 pipelined k-chunks. smem 202752 B
// ============================================================================
__device__ __forceinline__ void ff2_issue(float* wbuf, float* abuf, int c, int mblk,
    const float* __restrict__ Wout, const float* __restrict__ gt, int t)
{
    {
        int r = t >> 1, half = t & 1;
        char* dst = (char*)wbuf + r * 528 + half * 256;
        const char* src = (const char*)(Wout + ((size_t)(c * 128 + r)) * HH + half * 64);
        #pragma unroll
        for (int s = 0; s < 16; s++) cp16(dst + s * 16, src + s * 16);
    }
    {
        int r = t >> 2, q = t & 3;
        char* dst = (char*)abuf + r * 528 + q * 128;
        const char* src = (const char*)(gt + ((size_t)(mblk * 64 + r)) * FFW + c * 128 + q * 32);
        #pragma unroll
        for (int s = 0; s < 8; s++) cp16(dst + s * 16, src + s * 16);
    }
}

__global__ __launch_bounds__(256, 1) void k_ff2(
    const float* __restrict__ Wout, const float* __restrict__ bout,
    const float* __restrict__ maskV, float* __restrict__ out)
{
    extern __shared__ char smem[];
    float* sW0 = (float*)smem;
    float* sW1 = (float*)(smem + 67584);
    float* sA0 = (float*)(smem + 135168);
    float* sA1 = (float*)(smem + 168960);

    const int tid  = threadIdx.x;
    const int lane = tid & 31, wid = tid >> 5;
    const int g = lane >> 2, tg = lane & 3;
    const int wm = wid >> 2, wn = wid & 3;
    const int mblk = blockIdx.x;

    ff2_issue(sW0, sA0, 0, mblk, Wout, g_t, tid);
    CP_COMMIT();

    float acc[2][4][4];
    #pragma unroll
    for (int i = 0; i < 2; i++)
        #pragma unroll
        for (int j = 0; j < 4; j++)
            #pragma unroll
            for (int q = 0; q < 4; q++) acc[i][j][q] = 0.0f;

    #pragma unroll 1
    for (int c = 0; c < 4; c++) {
        if (c < 3) {
            float* wb = ((c + 1) & 1) ? sW1 : sW0;
            float* ab = ((c + 1) & 1) ? sA1 : sA0;
            ff2_issue(wb, ab, c + 1, mblk, Wout, g_t, tid);
        }
        CP_COMMIT();
        CP_WAIT1();
        __syncthreads();
        mma_block<2, 4, true, true>((c & 1) ? sA1 : sA0, 132,
                                    (c & 1) ? sW1 : sW0, 132, 16, 0,
                                    wm * 32, wn * 32, g, tg, acc);
        __syncthreads();
    }

    #pragma unroll
    for (int j = 0; j < 4; j++) {
        const int col = wn * 32 + j * 8 + 2 * tg;
        const float bb0 = bout[col], bb1 = bout[col + 1];
        #pragma unroll
        for (int i = 0; i < 2; i++) {
            const int row0 = mblk * 64 + wm * 32 + i * 16 + g;
            #pragma unroll
            for (int h = 0; h < 2; h++) {
                const int row = row0 + h * 8;
                const float mv = maskV[row];
                const size_t base = (size_t)row * HH + col;
                float v0 = acc[i][j][h * 2 + 0] + bb0 + g_h[base];
                float v1 = acc[i][j][h * 2 + 1] + bb1 + g_h[base + 1];
                float2* d = (float2*)(out + base);
                *d = make_float2(mv * v0, mv * v1);
            }
        }
    }
}

// ============================================================================
extern "C" void kernel_launch(void* const* d_in, const int* in_sizes, int n_in,
                              void* d_out, int out_size)
{
    const float* hV    = (const float*)d_in[0];
    const float* hE    = (const float*)d_in[1];
    const int*   Eidx  = (const int*)  d_in[2];
    const float* maskV = (const float*)d_in[3];
    const float* maskA = (const float*)d_in[4];
    const float* W1    = (const float*)d_in[5];
    const float* b1    = (const float*)d_in[6];
    const float* W2    = (const float*)d_in[7];
    const float* b2    = (const float*)d_in[8];
    const float* W3    = (const float*)d_in[9];
    const float* b3    = (const float*)d_in[10];
    const float* Win   = (const float*)d_in[11];
    const float* bin   = (const float*)d_in[12];
    const float* Wout  = (const float*)d_in[13];
    const float* bout  = (const float*)d_in[14];
    float* out = (float*)d_out;

    const int smE1 = 125952;
    const int smE2 = 120576;
    const int smF1 = 200704;
    const int smF2 = 202752;

    cudaFuncSetAttribute(k_edge1, cudaFuncAttributeMaxDynamicSharedMemorySize, smE1);
    cudaFuncSetAttribute(k_edge2, cudaFuncAttributeMaxDynamicSharedMemorySize, smE2);
    cudaFuncSetAttribute(k_ff1,   cudaFuncAttributeMaxDynamicSharedMemorySize, smF1);
    cudaFuncSetAttribute(k_ff2,   cudaFuncAttributeMaxDynamicSharedMemorySize, smF2);

    k_edge1<<<152, 512, smE1>>>(hV, hE, Eidx, W1, b1);
    k_edge2<<<152, 512, smE2>>>(hV, maskA, W2, b2, W3, b3);
    k_ff1  <<<128, 512, smF1>>>(Win, bin);
    k_ff2  <<<128, 256, smF2>>>(Wout, bout, maskV, out);
}